// round 6
// baseline (speedup 1.0000x reference)
#include <cuda_runtime.h>
#include <math.h>

#define EPSV 1e-8f

typedef unsigned long long ull;

namespace {
constexpr int B  = 32;
constexpr int S  = 64;
constexpr int H  = 200;
constexpr int L  = 20;
constexpr int HP = 202;      // full-H smem row stride (101 ull; 101%16=5 -> conflict-free)
constexpr int CHP = 102;     // chunked (50 h2) row stride (51 ull; 51%16=3 -> conflict-free)
constexpr int CS = 400;      // con_* inner stride (2*H)
constexpr int MV = 160;      // 8*L output columns
constexpr int PSIZE = B * S * MV;
constexpr int AST = 66;      // attderiv att/attT row stride
constexpr int VST = 104;     // attderiv V stride
constexpr int WST = 200;     // match W2 row stride
}

// packed f32x2 helpers (ptxas never auto-fuses these)
__device__ __forceinline__ void fma2(ull& d, ull a, ull b) {
    asm("fma.rn.f32x2 %0, %1, %2, %0;" : "+l"(d) : "l"(a), "l"(b));
}
__device__ __forceinline__ ull mul2(ull a, ull b) {
    ull r; asm("mul.rn.f32x2 %0, %1, %2;" : "=l"(r) : "l"(a), "l"(b)); return r;
}
__device__ __forceinline__ float red2(ull v) {
    float2 f = *reinterpret_cast<float2*>(&v);
    return f.x + f.y;
}

// ---------------- scratch (device globals; no allocation allowed) -------------
__device__ __align__(16) float g_att[2 * B * S * S];
__device__ __align__(16) float g_rowsum[2 * B * S];
__device__ __align__(16) float g_colsum[2 * B * S];
__device__ __align__(16) float g_amean_h[2 * B * S * H];
__device__ __align__(16) float g_amax_h [2 * B * S * H];
__device__ __align__(16) float g_amean_p[2 * B * S * H];
__device__ __align__(16) float g_amax_p [2 * B * S * H];

// ============================ Kernel A1: attention ===========================
// grid (B, 2), 256 threads, 16x16 grid, 4x4 tile, f32x2. Shuffle reductions.
__global__ void __launch_bounds__(256)
attn_kernel(const float* __restrict__ con_p,
            const float* __restrict__ con_h) {
    extern __shared__ float sm[];
    float* P     = sm;                 // S*HP
    float* Hm    = P  + S * HP;        // S*HP
    float* np    = Hm + S * HP;        // S
    float* nh    = np + S;             // S
    float* redCS = nh + S;             // S*8

    const int b = blockIdx.x, dir = blockIdx.y;
    const int tid = threadIdx.x;
    const float* pbase = con_p + (size_t)b * S * CS + dir * H;
    const float* hbase = con_h + (size_t)b * S * CS + dir * H;

    for (int i2 = tid; i2 < S * 100; i2 += 256) {
        int s = i2 / 100, h2 = i2 % 100;
        *reinterpret_cast<float2*>(P  + s * HP + 2 * h2) =
            *reinterpret_cast<const float2*>(pbase + s * CS + 2 * h2);
        *reinterpret_cast<float2*>(Hm + s * HP + 2 * h2) =
            *reinterpret_cast<const float2*>(hbase + s * CS + 2 * h2);
    }
    __syncthreads();

    if (tid < 64) {
        float acc = 0.f;
        #pragma unroll 4
        for (int k = 0; k < 100; k++) {
            float2 v = *reinterpret_cast<const float2*>(P + tid * HP + 2 * k);
            acc += v.x * v.x + v.y * v.y;
        }
        np[tid] = sqrtf(acc);
    } else if (tid < 128) {
        int q = tid - 64;
        float acc = 0.f;
        #pragma unroll 4
        for (int k = 0; k < 100; k++) {
            float2 v = *reinterpret_cast<const float2*>(Hm + q * HP + 2 * k);
            acc += v.x * v.x + v.y * v.y;
        }
        nh[q] = sqrtf(acc);
    }
    __syncthreads();

    const int tx = tid & 15, ty = tid >> 4;
    const int lane = tid & 31, warp = tid >> 5;
    const ull* Ap[4]; const ull* Bp[4];
    #pragma unroll
    for (int i = 0; i < 4; i++) Ap[i] = reinterpret_cast<const ull*>(P  + (ty + 16 * i) * HP);
    #pragma unroll
    for (int j = 0; j < 4; j++) Bp[j] = reinterpret_cast<const ull*>(Hm + (tx + 16 * j) * HP);

    ull acc2[4][4];
    #pragma unroll
    for (int i = 0; i < 4; i++)
        #pragma unroll
        for (int j = 0; j < 4; j++) acc2[i][j] = 0ull;

    ull ca[4], cb[4];
    #pragma unroll
    for (int i = 0; i < 4; i++) ca[i] = Ap[i][0];
    #pragma unroll
    for (int j = 0; j < 4; j++) cb[j] = Bp[j][0];

    #pragma unroll 2
    for (int h2 = 1; h2 < 100; h2++) {
        ull ta[4], tb[4];
        #pragma unroll
        for (int i = 0; i < 4; i++) ta[i] = Ap[i][h2];
        #pragma unroll
        for (int j = 0; j < 4; j++) tb[j] = Bp[j][h2];
        #pragma unroll
        for (int i = 0; i < 4; i++)
            #pragma unroll
            for (int j = 0; j < 4; j++) fma2(acc2[i][j], ca[i], cb[j]);
        #pragma unroll
        for (int i = 0; i < 4; i++) ca[i] = ta[i];
        #pragma unroll
        for (int j = 0; j < 4; j++) cb[j] = tb[j];
    }
    #pragma unroll
    for (int i = 0; i < 4; i++)
        #pragma unroll
        for (int j = 0; j < 4; j++) fma2(acc2[i][j], ca[i], cb[j]);

    float* gatt = g_att + (size_t)(dir * B + b) * S * S;
    float rsum[4], csum[4];
    #pragma unroll
    for (int i = 0; i < 4; i++) rsum[i] = 0.f;
    #pragma unroll
    for (int j = 0; j < 4; j++) csum[j] = 0.f;

    #pragma unroll
    for (int i = 0; i < 4; i++) {
        int p = ty + 16 * i;
        #pragma unroll
        for (int j = 0; j < 4; j++) {
            int q = tx + 16 * j;
            float d = np[p] * nh[q];
            float c = red2(acc2[i][j]) / (d > EPSV ? d : EPSV);
            gatt[p * S + q] = c;
            rsum[i] += c;
            csum[j] += c;
        }
    }
    #pragma unroll
    for (int m = 1; m <= 8; m <<= 1)
        #pragma unroll
        for (int i = 0; i < 4; i++)
            rsum[i] += __shfl_xor_sync(0xffffffffu, rsum[i], m);
    if (tx == 0) {
        #pragma unroll
        for (int i = 0; i < 4; i++)
            g_rowsum[(dir * B + b) * S + (ty + 16 * i)] = rsum[i];
    }
    #pragma unroll
    for (int j = 0; j < 4; j++)
        csum[j] += __shfl_xor_sync(0xffffffffu, csum[j], 16);
    if (lane < 16) {
        #pragma unroll
        for (int j = 0; j < 4; j++)
            redCS[(tx + 16 * j) * 8 + warp] = csum[j];
    }
    __syncthreads();
    if (tid < 64) {
        float s0 = 0.f;
        #pragma unroll
        for (int k = 0; k < 8; k++) s0 += redCS[tid * 8 + k];
        g_colsum[(dir * B + b) * S + tid] = s0;
    }
}

// ===================== Kernel A2: att mean/max vectors =======================
__global__ void __launch_bounds__(256)
attderiv_kernel(const float* __restrict__ con_p,
                const float* __restrict__ con_h) {
    extern __shared__ float sm[];
    float* att  = sm;                    // S*AST
    float* attT = att + S * AST;         // S*AST
    float* V    = attT + S * AST;        // S*VST
    float* dsum = V + S * VST;           // S

    const int b = blockIdx.x, dir = blockIdx.y;
    const int side = blockIdx.z >> 1;
    const int ck = blockIdx.z & 1;
    const int h0 = ck * 100;
    const int tid = threadIdx.x;

    const float* gatt = g_att + (size_t)(dir * B + b) * S * S;
    for (int i = tid; i < S * S; i += 256) {
        int p = i >> 6, q = i & 63;
        float v = gatt[i];
        att [p * AST + q] = v;
        attT[q * AST + p] = v;
    }

    const float* src = (side == 0 ? con_h : con_p) + (size_t)b * S * CS + dir * H + h0;
    for (int i4 = tid; i4 < S * 25; i4 += 256) {
        int s = i4 / 25, c4 = i4 % 25;
        *reinterpret_cast<float4*>(V + s * VST + c4 * 4) =
            *reinterpret_cast<const float4*>(src + s * CS + c4 * 4);
    }
    if (tid < S)
        dsum[tid] = (side == 0 ? g_rowsum : g_colsum)[(dir * B + b) * S + tid];
    __syncthreads();

    float* gmean = (side == 0 ? g_amean_h : g_amean_p) + (size_t)(dir * B + b) * S * H + h0;
    float* gmax  = (side == 0 ? g_amax_h  : g_amax_p ) + (size_t)(dir * B + b) * S * H + h0;

    if (tid < 200) {
        const int oi = tid / 25, hi = tid % 25;
        const int o0 = oi * 8, hb = hi * 4;
        const float* M = (side == 0) ? att : attT;   // M[o][q]

        float ss[8][4], sx[8][4];
        #pragma unroll
        for (int io = 0; io < 8; io++)
            #pragma unroll
            for (int k = 0; k < 4; k++) { ss[io][k] = 0.f; sx[io][k] = -INFINITY; }

        for (int q2 = 0; q2 < 32; q2++) {
            const int q = 2 * q2;
            float2 av[8];
            #pragma unroll
            for (int io = 0; io < 8; io++)
                av[io] = *reinterpret_cast<const float2*>(M + (o0 + io) * AST + q);
            float4 v0 = *reinterpret_cast<const float4*>(V + q * VST + hb);
            float4 v1 = *reinterpret_cast<const float4*>(V + (q + 1) * VST + hb);
            float vv0[4] = {v0.x, v0.y, v0.z, v0.w};
            float vv1[4] = {v1.x, v1.y, v1.z, v1.w};
            #pragma unroll
            for (int io = 0; io < 8; io++) {
                float ax = av[io].x, ay = av[io].y;
                #pragma unroll
                for (int k = 0; k < 4; k++) {
                    float t0 = ax * vv0[k];
                    float t1 = ay * vv1[k];
                    ss[io][k] += t0 + t1;
                    sx[io][k] = fmaxf(sx[io][k], fmaxf(t0, t1));
                }
            }
        }
        #pragma unroll
        for (int io = 0; io < 8; io++) {
            float d = dsum[o0 + io];
            float inv = 1.f / (d > EPSV ? d : EPSV);
            float4 m4, x4;
            m4.x = ss[io][0] * inv; m4.y = ss[io][1] * inv;
            m4.z = ss[io][2] * inv; m4.w = ss[io][3] * inv;
            x4.x = sx[io][0]; x4.y = sx[io][1]; x4.z = sx[io][2]; x4.w = sx[io][3];
            *reinterpret_cast<float4*>(gmean + (o0 + io) * H + hb) = m4;
            *reinterpret_cast<float4*>(gmax  + (o0 + io) * H + hb) = x4;
        }
    }
}

// ================== Kernel B1: "full" mp_match (kind 0) =====================
// grid (B, 4, 2): y = side*2 + dir, z = s-half. Independent of attention.
__global__ void __launch_bounds__(128)
match_full_kernel(const float* __restrict__ con_p,
                  const float* __restrict__ con_h,
                  const float* __restrict__ w1, const float* __restrict__ w2,
                  float* __restrict__ out) {
    extern __shared__ float sm[];
    float* V1 = sm;                 // 32*HP
    float* V2 = V1 + 32 * HP;       // HP (single row)
    float* W2 = V2 + HP;            // L*WST

    const int b = blockIdx.x;
    const int side = blockIdx.y >> 1;
    const int dir = blockIdx.y & 1;
    const int shalf = blockIdx.z;
    const int tid = threadIdx.x;
    const int s0 = shalf * 32;

    const float* v1 = (side == 0 ? con_p : con_h) + (size_t)b * S * CS + dir * H;
    for (int i2 = tid; i2 < 32 * 100; i2 += 128) {
        int s = i2 / 100, h2 = i2 % 100;
        *reinterpret_cast<float2*>(V1 + s * HP + 2 * h2) =
            *reinterpret_cast<const float2*>(v1 + (s0 + s) * CS + 2 * h2);
    }
    const float* v2 = (side == 0 ? con_h : con_p)
                    + (size_t)b * S * CS + (dir == 0 ? (S - 1) : 0) * CS + dir * H;
    for (int h2 = tid; h2 < 100; h2 += 128)
        *reinterpret_cast<float2*>(V2 + 2 * h2) =
            *reinterpret_cast<const float2*>(v2 + 2 * h2);

    const float* w = (dir == 0 ? w1 : w2);
    for (int i2 = tid; i2 < L * 100; i2 += 128) {
        int l = i2 / 100, h2 = i2 % 100;
        float2 wv = *reinterpret_cast<const float2*>(w + l * H + 2 * h2);
        float2 sq; sq.x = wv.x * wv.x; sq.y = wv.y * wv.y;
        *reinterpret_cast<float2*>(W2 + l * WST + 2 * h2) = sq;
    }
    __syncthreads();

    const int tx = tid & 3;        // l group: l = tx*5 + il
    const int ty = tid >> 2;       // s = s0 + ty

    const ull* Ap = reinterpret_cast<const ull*>(V1 + ty * HP);
    const ull* Bp = reinterpret_cast<const ull*>(V2);
    const ull* Wp[5];
    #pragma unroll
    for (int il = 0; il < 5; il++)
        Wp[il] = reinterpret_cast<const ull*>(W2 + (tx * 5 + il) * WST);

    ull dacc[5], naa[5], nbb[5];
    #pragma unroll
    for (int il = 0; il < 5; il++) { dacc[il] = 0ull; naa[il] = 0ull; nbb[il] = 0ull; }

    #pragma unroll 2
    for (int h2 = 0; h2 < 100; h2++) {
        ull a = Ap[h2], bb = Bp[h2];
        ull u1 = mul2(a, bb), u2 = mul2(a, a), u3 = mul2(bb, bb);
        #pragma unroll
        for (int il = 0; il < 5; il++) {
            ull wv = Wp[il][h2];
            fma2(dacc[il], u1, wv);
            fma2(naa[il], u2, wv);
            fma2(nbb[il], u3, wv);
        }
    }

    const int col = dir * 80;
    float* obase = out + (size_t)side * PSIZE + (size_t)b * S * MV;
    #pragma unroll
    for (int il = 0; il < 5; il++) {
        float d = sqrtf(red2(naa[il])) * sqrtf(red2(nbb[il]));
        obase[(s0 + ty) * MV + col + (tx * 5 + il)] = red2(dacc[il]) / fmaxf(d, EPSV);
    }
}

// ================ Kernel B2: att mean/max mp_match (kinds 1,2) ===============
// grid (B, 8, 2): y = side*4 + (kind-1)*2 + dir, z = s-half.
__global__ void __launch_bounds__(128)
match_att_kernel(const float* __restrict__ con_p,
                 const float* __restrict__ con_h,
                 const float* __restrict__ w5, const float* __restrict__ w6,
                 const float* __restrict__ w7, const float* __restrict__ w8,
                 float* __restrict__ out) {
    extern __shared__ float sm[];
    float* V1 = sm;                 // 32*HP
    float* V2 = V1 + 32 * HP;       // 32*HP
    float* W2 = V2 + 32 * HP;       // L*WST

    const int b = blockIdx.x;
    const int side = blockIdx.y >> 2;
    const int kind = 1 + ((blockIdx.y >> 1) & 1);
    const int dir = blockIdx.y & 1;
    const int shalf = blockIdx.z;
    const int tid = threadIdx.x;
    const int s0 = shalf * 32;

    const float* v1 = (side == 0 ? con_p : con_h) + (size_t)b * S * CS + dir * H;
    for (int i2 = tid; i2 < 32 * 100; i2 += 128) {
        int s = i2 / 100, h2 = i2 % 100;
        *reinterpret_cast<float2*>(V1 + s * HP + 2 * h2) =
            *reinterpret_cast<const float2*>(v1 + (s0 + s) * CS + 2 * h2);
    }
    const float* v2 = (kind == 1 ? (side == 0 ? g_amean_h : g_amean_p)
                                 : (side == 0 ? g_amax_h  : g_amax_p))
                    + (size_t)(dir * B + b) * S * H;
    for (int i2 = tid; i2 < 32 * 100; i2 += 128) {
        int s = i2 / 100, h2 = i2 % 100;
        *reinterpret_cast<float2*>(V2 + s * HP + 2 * h2) =
            *reinterpret_cast<const float2*>(v2 + (s0 + s) * H + 2 * h2);
    }

    const float* w = (kind == 1 ? (dir == 0 ? w5 : w6) : (dir == 0 ? w7 : w8));
    for (int i2 = tid; i2 < L * 100; i2 += 128) {
        int l = i2 / 100, h2 = i2 % 100;
        float2 wv = *reinterpret_cast<const float2*>(w + l * H + 2 * h2);
        float2 sq; sq.x = wv.x * wv.x; sq.y = wv.y * wv.y;
        *reinterpret_cast<float2*>(W2 + l * WST + 2 * h2) = sq;
    }
    __syncthreads();

    const int tx = tid & 3;
    const int ty = tid >> 2;

    const ull* Ap = reinterpret_cast<const ull*>(V1 + ty * HP);
    const ull* Bp = reinterpret_cast<const ull*>(V2 + ty * HP);
    const ull* Wp[5];
    #pragma unroll
    for (int il = 0; il < 5; il++)
        Wp[il] = reinterpret_cast<const ull*>(W2 + (tx * 5 + il) * WST);

    ull dacc[5], naa[5], nbb[5];
    #pragma unroll
    for (int il = 0; il < 5; il++) { dacc[il] = 0ull; naa[il] = 0ull; nbb[il] = 0ull; }

    #pragma unroll 2
    for (int h2 = 0; h2 < 100; h2++) {
        ull a = Ap[h2], bb = Bp[h2];
        ull u1 = mul2(a, bb), u2 = mul2(a, a), u3 = mul2(bb, bb);
        #pragma unroll
        for (int il = 0; il < 5; il++) {
            ull wv = Wp[il][h2];
            fma2(dacc[il], u1, wv);
            fma2(naa[il], u2, wv);
            fma2(nbb[il], u3, wv);
        }
    }

    const int col = (kind == 1 ? 40 : 60) + dir * 80;
    float* obase = out + (size_t)side * PSIZE + (size_t)b * S * MV;
    #pragma unroll
    for (int il = 0; il < 5; il++) {
        float d = sqrtf(red2(naa[il])) * sqrtf(red2(nbb[il]));
        obase[(s0 + ty) * MV + col + (tx * 5 + il)] = red2(dacc[il]) / fmaxf(d, EPSV);
    }
}

// ================= Kernel C: pairwise mp + max reductions ====================
// grid (B, L, 2), 128 threads, 8x4 tile, h chunked in 2 (smem 54.6KB -> 4 blk/SM).
__global__ void __launch_bounds__(128, 4)
pairwise_kernel(const float* __restrict__ con_p,
                const float* __restrict__ con_h,
                const float* __restrict__ w3,
                const float* __restrict__ w4,
                float* __restrict__ out) {
    extern __shared__ float sm[];
    float* A    = sm;                 // S*CHP (p * w_l, half-H chunk)
    float* Bm   = A + S * CHP;        // S*CHP
    float* na   = Bm + S * CHP;       // S
    float* nb   = na + S;             // S
    float* wsh  = nb + S;             // H
    float* redQ = wsh + H;            // S*4

    const int b = blockIdx.x, l = blockIdx.y, dir = blockIdx.z;
    const int tid = threadIdx.x;

    const float* w = (dir == 0 ? w3 : w4) + l * H;
    for (int h2 = tid; h2 < 100; h2 += 128)
        *reinterpret_cast<float2*>(wsh + 2 * h2) =
            *reinterpret_cast<const float2*>(w + 2 * h2);

    const float* pb = con_p + (size_t)b * S * CS + dir * H;
    const float* hb = con_h + (size_t)b * S * CS + dir * H;

    const int tx = tid & 15, ty = tid >> 4;
    const int lane = tid & 31, warp = tid >> 5;
    const ull* Ap[8]; const ull* Bp[4];
    #pragma unroll
    for (int i = 0; i < 8; i++) Ap[i] = reinterpret_cast<const ull*>(A  + (ty + 8 * i) * CHP);
    #pragma unroll
    for (int j = 0; j < 4; j++) Bp[j] = reinterpret_cast<const ull*>(Bm + (tx + 16 * j) * CHP);

    ull acc2[8][4];
    #pragma unroll
    for (int i = 0; i < 8; i++)
        #pragma unroll
        for (int j = 0; j < 4; j++) acc2[i][j] = 0ull;

    float nacc = 0.f;   // tid<64: row-tid |a|^2 ; tid>=64: row-(tid-64) |b|^2

    for (int c = 0; c < 2; c++) {
        __syncthreads();   // protects previous chunk's readers (no-op on c==0 wrt data)
        const int hbase = c * 50;
        for (int i2 = tid; i2 < S * 50; i2 += 128) {
            int s = i2 / 50, hl = i2 % 50;
            int h2 = hbase + hl;
            float2 wv = *reinterpret_cast<const float2*>(wsh + 2 * h2);
            float2 pv = *reinterpret_cast<const float2*>(pb + s * CS + 2 * h2);
            float2 hv = *reinterpret_cast<const float2*>(hb + s * CS + 2 * h2);
            pv.x *= wv.x; pv.y *= wv.y;
            hv.x *= wv.x; hv.y *= wv.y;
            *reinterpret_cast<float2*>(A  + s * CHP + 2 * hl) = pv;
            *reinterpret_cast<float2*>(Bm + s * CHP + 2 * hl) = hv;
        }
        __syncthreads();

        // norm partials
        {
            const float* row = (tid < 64) ? (A + tid * CHP) : (Bm + (tid - 64) * CHP);
            #pragma unroll 4
            for (int k = 0; k < 50; k++) {
                float2 v = *reinterpret_cast<const float2*>(row + 2 * k);
                nacc += v.x * v.x + v.y * v.y;
            }
        }

        // dot accumulation with prefetch
        ull ca[8], cb[4];
        #pragma unroll
        for (int i = 0; i < 8; i++) ca[i] = Ap[i][0];
        #pragma unroll
        for (int j = 0; j < 4; j++) cb[j] = Bp[j][0];
        #pragma unroll 2
        for (int h2 = 1; h2 < 50; h2++) {
            ull ta[8], tb[4];
            #pragma unroll
            for (int i = 0; i < 8; i++) ta[i] = Ap[i][h2];
            #pragma unroll
            for (int j = 0; j < 4; j++) tb[j] = Bp[j][h2];
            #pragma unroll
            for (int i = 0; i < 8; i++)
                #pragma unroll
                for (int j = 0; j < 4; j++) fma2(acc2[i][j], ca[i], cb[j]);
            #pragma unroll
            for (int i = 0; i < 8; i++) ca[i] = ta[i];
            #pragma unroll
            for (int j = 0; j < 4; j++) cb[j] = tb[j];
        }
        #pragma unroll
        for (int i = 0; i < 8; i++)
            #pragma unroll
            for (int j = 0; j < 4; j++) fma2(acc2[i][j], ca[i], cb[j]);
    }

    if (tid < 64) na[tid] = sqrtf(nacc);
    else          nb[tid - 64] = sqrtf(nacc);
    __syncthreads();

    float pmax[8], qmax[4];
    #pragma unroll
    for (int i = 0; i < 8; i++) pmax[i] = -INFINITY;
    #pragma unroll
    for (int j = 0; j < 4; j++) qmax[j] = -INFINITY;

    #pragma unroll
    for (int i = 0; i < 8; i++) {
        int p = ty + 8 * i;
        #pragma unroll
        for (int j = 0; j < 4; j++) {
            int q = tx + 16 * j;
            float d = na[p] * nb[q];
            float c = red2(acc2[i][j]) / (d > EPSV ? d : EPSV);
            pmax[i] = fmaxf(pmax[i], c);
            qmax[j] = fmaxf(qmax[j], c);
        }
    }

    const int colbase = (dir == 0 ? 20 : 100) + l;
    // row max: reduce over tx within 16-lane groups
    #pragma unroll
    for (int m = 1; m <= 8; m <<= 1)
        #pragma unroll
        for (int i = 0; i < 8; i++)
            pmax[i] = fmaxf(pmax[i], __shfl_xor_sync(0xffffffffu, pmax[i], m));
    if (tx == 0) {
        #pragma unroll
        for (int i = 0; i < 8; i++)
            out[((size_t)b * S + (ty + 8 * i)) * MV + colbase] = pmax[i];    // mv_p
    }
    // col max: combine two ty's in-warp, then cross-warp via smem (4 warps)
    #pragma unroll
    for (int j = 0; j < 4; j++)
        qmax[j] = fmaxf(qmax[j], __shfl_xor_sync(0xffffffffu, qmax[j], 16));
    if (lane < 16) {
        #pragma unroll
        for (int j = 0; j < 4; j++)
            redQ[(tx + 16 * j) * 4 + warp] = qmax[j];
    }
    __syncthreads();
    if (tid < 64) {
        float m = -INFINITY;
        #pragma unroll
        for (int k = 0; k < 4; k++) m = fmaxf(m, redQ[tid * 4 + k]);
        out[(size_t)PSIZE + ((size_t)b * S + tid) * MV + colbase] = m;       // mv_h
    }
}

// ================================ launcher ===================================
extern "C" void kernel_launch(void* const* d_in, const int* in_sizes, int n_in,
                              void* d_out, int out_size) {
    const float* con_p = (const float*)d_in[0];
    const float* con_h = (const float*)d_in[1];
    const float* w1 = (const float*)d_in[2];
    const float* w2 = (const float*)d_in[3];
    const float* w3 = (const float*)d_in[4];
    const float* w4 = (const float*)d_in[5];
    const float* w5 = (const float*)d_in[6];
    const float* w6 = (const float*)d_in[7];
    const float* w7 = (const float*)d_in[8];
    const float* w8 = (const float*)d_in[9];
    float* out = (float*)d_out;

    constexpr size_t SM_A1 = (size_t)(2 * S * HP + 2 * S + S * 8) * sizeof(float);
    constexpr size_t SM_A2 = (size_t)(2 * S * AST + S * VST + S) * sizeof(float);
    constexpr size_t SM_BF = (size_t)(32 * HP + HP + L * WST) * sizeof(float);
    constexpr size_t SM_BA = (size_t)(2 * 32 * HP + L * WST) * sizeof(float);
    constexpr size_t SM_C  = (size_t)(2 * S * CHP + 2 * S + H + S * 4) * sizeof(float);

    static cudaStream_t s2 = nullptr;
    static cudaEvent_t evFork = nullptr, evJoin = nullptr;
    static bool init_done = false;
    if (!init_done) {
        cudaFuncSetAttribute(attn_kernel,       cudaFuncAttributeMaxDynamicSharedMemorySize, (int)SM_A1);
        cudaFuncSetAttribute(attderiv_kernel,   cudaFuncAttributeMaxDynamicSharedMemorySize, (int)SM_A2);
        cudaFuncSetAttribute(match_full_kernel, cudaFuncAttributeMaxDynamicSharedMemorySize, (int)SM_BF);
        cudaFuncSetAttribute(match_att_kernel,  cudaFuncAttributeMaxDynamicSharedMemorySize, (int)SM_BA);
        cudaFuncSetAttribute(pairwise_kernel,   cudaFuncAttributeMaxDynamicSharedMemorySize, (int)SM_C);
        cudaStreamCreateWithFlags(&s2, cudaStreamNonBlocking);
        cudaEventCreateWithFlags(&evFork, cudaEventDisableTiming);
        cudaEventCreateWithFlags(&evJoin, cudaEventDisableTiming);
        init_done = true;
    }

    // Fork: pairwise (cols 20-39/100-119) on s2; everything else chained on 0.
    cudaEventRecord(evFork, 0);
    cudaStreamWaitEvent(s2, evFork, 0);
    pairwise_kernel<<<dim3(B, L, 2), 128, SM_C, s2>>>(con_p, con_h, w3, w4, out);

    match_full_kernel<<<dim3(B, 4, 2), 128, SM_BF>>>(con_p, con_h, w1, w2, out);
    attn_kernel<<<dim3(B, 2), 256, SM_A1>>>(con_p, con_h);
    attderiv_kernel<<<dim3(B, 2, 4), 256, SM_A2>>>(con_p, con_h);
    match_att_kernel<<<dim3(B, 8, 2), 128, SM_BA>>>(con_p, con_h, w5, w6, w7, w8, out);

    cudaEventRecord(evJoin, s2);
    cudaStreamWaitEvent(0, evJoin, 0);
}

// round 7
// speedup vs baseline: 1.0159x; 1.0159x over previous
#include <cuda_runtime.h>
#include <math.h>

#define EPSV 1e-8f

typedef unsigned long long ull;

namespace {
constexpr int B  = 32;
constexpr int S  = 64;
constexpr int H  = 200;
constexpr int L  = 20;
constexpr int HP = 202;      // smem row stride (101 ull; 101%16=5 -> conflict-free)
constexpr int CS = 400;      // con_* inner stride (2*H)
constexpr int MV = 160;      // 8*L output columns
constexpr int PSIZE = B * S * MV;
constexpr int AST = 66;      // attderiv att/attT row stride
constexpr int VST = 104;     // attderiv V stride
constexpr int WST = 200;     // match W2 row stride
}

// packed f32x2 helpers (ptxas never auto-fuses these)
__device__ __forceinline__ void fma2(ull& d, ull a, ull b) {
    asm("fma.rn.f32x2 %0, %1, %2, %0;" : "+l"(d) : "l"(a), "l"(b));
}
__device__ __forceinline__ ull mul2(ull a, ull b) {
    ull r; asm("mul.rn.f32x2 %0, %1, %2;" : "=l"(r) : "l"(a), "l"(b)); return r;
}
__device__ __forceinline__ float red2(ull v) {
    float2 f = *reinterpret_cast<float2*>(&v);
    return f.x + f.y;
}

// ---------------- scratch (device globals; no allocation allowed) -------------
__device__ __align__(16) float g_att[2 * B * S * S];
__device__ __align__(16) float g_rowsum[2 * B * S];
__device__ __align__(16) float g_colsum[2 * B * S];
__device__ __align__(16) float g_amean_h[2 * B * S * H];
__device__ __align__(16) float g_amax_h [2 * B * S * H];
__device__ __align__(16) float g_amean_p[2 * B * S * H];
__device__ __align__(16) float g_amax_p [2 * B * S * H];

// ============================ Kernel A1: attention ===========================
// grid (B, 2), 256 threads, 16x16 grid, 4x4 tile, f32x2. Shuffle reductions.
__global__ void __launch_bounds__(256)
attn_kernel(const float* __restrict__ con_p,
            const float* __restrict__ con_h) {
    extern __shared__ float sm[];
    float* P     = sm;                 // S*HP
    float* Hm    = P  + S * HP;        // S*HP
    float* np    = Hm + S * HP;        // S
    float* nh    = np + S;             // S
    float* redCS = nh + S;             // S*8

    const int b = blockIdx.x, dir = blockIdx.y;
    const int tid = threadIdx.x;
    const float* pbase = con_p + (size_t)b * S * CS + dir * H;
    const float* hbase = con_h + (size_t)b * S * CS + dir * H;

    for (int i2 = tid; i2 < S * 100; i2 += 256) {
        int s = i2 / 100, h2 = i2 % 100;
        *reinterpret_cast<float2*>(P  + s * HP + 2 * h2) =
            *reinterpret_cast<const float2*>(pbase + s * CS + 2 * h2);
        *reinterpret_cast<float2*>(Hm + s * HP + 2 * h2) =
            *reinterpret_cast<const float2*>(hbase + s * CS + 2 * h2);
    }
    __syncthreads();

    if (tid < 64) {
        float acc = 0.f;
        #pragma unroll 4
        for (int k = 0; k < 100; k++) {
            float2 v = *reinterpret_cast<const float2*>(P + tid * HP + 2 * k);
            acc += v.x * v.x + v.y * v.y;
        }
        np[tid] = sqrtf(acc);
    } else if (tid < 128) {
        int q = tid - 64;
        float acc = 0.f;
        #pragma unroll 4
        for (int k = 0; k < 100; k++) {
            float2 v = *reinterpret_cast<const float2*>(Hm + q * HP + 2 * k);
            acc += v.x * v.x + v.y * v.y;
        }
        nh[q] = sqrtf(acc);
    }
    __syncthreads();

    const int tx = tid & 15, ty = tid >> 4;
    const int lane = tid & 31, warp = tid >> 5;
    const ull* Ap[4]; const ull* Bp[4];
    #pragma unroll
    for (int i = 0; i < 4; i++) Ap[i] = reinterpret_cast<const ull*>(P  + (ty + 16 * i) * HP);
    #pragma unroll
    for (int j = 0; j < 4; j++) Bp[j] = reinterpret_cast<const ull*>(Hm + (tx + 16 * j) * HP);

    ull acc2[4][4];
    #pragma unroll
    for (int i = 0; i < 4; i++)
        #pragma unroll
        for (int j = 0; j < 4; j++) acc2[i][j] = 0ull;

    ull ca[4], cb[4];
    #pragma unroll
    for (int i = 0; i < 4; i++) ca[i] = Ap[i][0];
    #pragma unroll
    for (int j = 0; j < 4; j++) cb[j] = Bp[j][0];

    #pragma unroll 2
    for (int h2 = 1; h2 < 100; h2++) {
        ull ta[4], tb[4];
        #pragma unroll
        for (int i = 0; i < 4; i++) ta[i] = Ap[i][h2];
        #pragma unroll
        for (int j = 0; j < 4; j++) tb[j] = Bp[j][h2];
        #pragma unroll
        for (int i = 0; i < 4; i++)
            #pragma unroll
            for (int j = 0; j < 4; j++) fma2(acc2[i][j], ca[i], cb[j]);
        #pragma unroll
        for (int i = 0; i < 4; i++) ca[i] = ta[i];
        #pragma unroll
        for (int j = 0; j < 4; j++) cb[j] = tb[j];
    }
    #pragma unroll
    for (int i = 0; i < 4; i++)
        #pragma unroll
        for (int j = 0; j < 4; j++) fma2(acc2[i][j], ca[i], cb[j]);

    float* gatt = g_att + (size_t)(dir * B + b) * S * S;
    float rsum[4], csum[4];
    #pragma unroll
    for (int i = 0; i < 4; i++) rsum[i] = 0.f;
    #pragma unroll
    for (int j = 0; j < 4; j++) csum[j] = 0.f;

    #pragma unroll
    for (int i = 0; i < 4; i++) {
        int p = ty + 16 * i;
        #pragma unroll
        for (int j = 0; j < 4; j++) {
            int q = tx + 16 * j;
            float d = np[p] * nh[q];
            float c = red2(acc2[i][j]) / (d > EPSV ? d : EPSV);
            gatt[p * S + q] = c;
            rsum[i] += c;
            csum[j] += c;
        }
    }
    #pragma unroll
    for (int m = 1; m <= 8; m <<= 1)
        #pragma unroll
        for (int i = 0; i < 4; i++)
            rsum[i] += __shfl_xor_sync(0xffffffffu, rsum[i], m);
    if (tx == 0) {
        #pragma unroll
        for (int i = 0; i < 4; i++)
            g_rowsum[(dir * B + b) * S + (ty + 16 * i)] = rsum[i];
    }
    #pragma unroll
    for (int j = 0; j < 4; j++)
        csum[j] += __shfl_xor_sync(0xffffffffu, csum[j], 16);
    if (lane < 16) {
        #pragma unroll
        for (int j = 0; j < 4; j++)
            redCS[(tx + 16 * j) * 8 + warp] = csum[j];
    }
    __syncthreads();
    if (tid < 64) {
        float s0 = 0.f;
        #pragma unroll
        for (int k = 0; k < 8; k++) s0 += redCS[tid * 8 + k];
        g_colsum[(dir * B + b) * S + tid] = s0;
    }
}

// ===================== Kernel A2: att mean/max vectors =======================
__global__ void __launch_bounds__(256)
attderiv_kernel(const float* __restrict__ con_p,
                const float* __restrict__ con_h) {
    extern __shared__ float sm[];
    float* att  = sm;                    // S*AST
    float* attT = att + S * AST;         // S*AST
    float* V    = attT + S * AST;        // S*VST
    float* dsum = V + S * VST;           // S

    const int b = blockIdx.x, dir = blockIdx.y;
    const int side = blockIdx.z >> 1;
    const int ck = blockIdx.z & 1;
    const int h0 = ck * 100;
    const int tid = threadIdx.x;

    const float* gatt = g_att + (size_t)(dir * B + b) * S * S;
    for (int i = tid; i < S * S; i += 256) {
        int p = i >> 6, q = i & 63;
        float v = gatt[i];
        att [p * AST + q] = v;
        attT[q * AST + p] = v;
    }

    const float* src = (side == 0 ? con_h : con_p) + (size_t)b * S * CS + dir * H + h0;
    for (int i4 = tid; i4 < S * 25; i4 += 256) {
        int s = i4 / 25, c4 = i4 % 25;
        *reinterpret_cast<float4*>(V + s * VST + c4 * 4) =
            *reinterpret_cast<const float4*>(src + s * CS + c4 * 4);
    }
    if (tid < S)
        dsum[tid] = (side == 0 ? g_rowsum : g_colsum)[(dir * B + b) * S + tid];
    __syncthreads();

    float* gmean = (side == 0 ? g_amean_h : g_amean_p) + (size_t)(dir * B + b) * S * H + h0;
    float* gmax  = (side == 0 ? g_amax_h  : g_amax_p ) + (size_t)(dir * B + b) * S * H + h0;

    if (tid < 200) {
        const int oi = tid / 25, hi = tid % 25;
        const int o0 = oi * 8, hb = hi * 4;
        const float* M = (side == 0) ? att : attT;   // M[o][q]

        float ss[8][4], sx[8][4];
        #pragma unroll
        for (int io = 0; io < 8; io++)
            #pragma unroll
            for (int k = 0; k < 4; k++) { ss[io][k] = 0.f; sx[io][k] = -INFINITY; }

        for (int q2 = 0; q2 < 32; q2++) {
            const int q = 2 * q2;
            float2 av[8];
            #pragma unroll
            for (int io = 0; io < 8; io++)
                av[io] = *reinterpret_cast<const float2*>(M + (o0 + io) * AST + q);
            float4 v0 = *reinterpret_cast<const float4*>(V + q * VST + hb);
            float4 v1 = *reinterpret_cast<const float4*>(V + (q + 1) * VST + hb);
            float vv0[4] = {v0.x, v0.y, v0.z, v0.w};
            float vv1[4] = {v1.x, v1.y, v1.z, v1.w};
            #pragma unroll
            for (int io = 0; io < 8; io++) {
                float ax = av[io].x, ay = av[io].y;
                #pragma unroll
                for (int k = 0; k < 4; k++) {
                    float t0 = ax * vv0[k];
                    float t1 = ay * vv1[k];
                    ss[io][k] += t0 + t1;
                    sx[io][k] = fmaxf(sx[io][k], fmaxf(t0, t1));
                }
            }
        }
        #pragma unroll
        for (int io = 0; io < 8; io++) {
            float d = dsum[o0 + io];
            float inv = 1.f / (d > EPSV ? d : EPSV);
            float4 m4, x4;
            m4.x = ss[io][0] * inv; m4.y = ss[io][1] * inv;
            m4.z = ss[io][2] * inv; m4.w = ss[io][3] * inv;
            x4.x = sx[io][0]; x4.y = sx[io][1]; x4.z = sx[io][2]; x4.w = sx[io][3];
            *reinterpret_cast<float4*>(gmean + (o0 + io) * H + hb) = m4;
            *reinterpret_cast<float4*>(gmax  + (o0 + io) * H + hb) = x4;
        }
    }
}

// ================== Kernel B1: "full" mp_match (kind 0) =====================
// grid (B, 4, 2): y = side*2 + dir, z = s-half. Independent of attention.
__global__ void __launch_bounds__(128)
match_full_kernel(const float* __restrict__ con_p,
                  const float* __restrict__ con_h,
                  const float* __restrict__ w1, const float* __restrict__ w2,
                  float* __restrict__ out) {
    extern __shared__ float sm[];
    float* V1 = sm;                 // 32*HP
    float* V2 = V1 + 32 * HP;       // HP (single row)
    float* W2 = V2 + HP;            // L*WST

    const int b = blockIdx.x;
    const int side = blockIdx.y >> 1;
    const int dir = blockIdx.y & 1;
    const int shalf = blockIdx.z;
    const int tid = threadIdx.x;
    const int s0 = shalf * 32;

    const float* v1 = (side == 0 ? con_p : con_h) + (size_t)b * S * CS + dir * H;
    for (int i2 = tid; i2 < 32 * 100; i2 += 128) {
        int s = i2 / 100, h2 = i2 % 100;
        *reinterpret_cast<float2*>(V1 + s * HP + 2 * h2) =
            *reinterpret_cast<const float2*>(v1 + (s0 + s) * CS + 2 * h2);
    }
    const float* v2 = (side == 0 ? con_h : con_p)
                    + (size_t)b * S * CS + (dir == 0 ? (S - 1) : 0) * CS + dir * H;
    for (int h2 = tid; h2 < 100; h2 += 128)
        *reinterpret_cast<float2*>(V2 + 2 * h2) =
            *reinterpret_cast<const float2*>(v2 + 2 * h2);

    const float* w = (dir == 0 ? w1 : w2);
    for (int i2 = tid; i2 < L * 100; i2 += 128) {
        int l = i2 / 100, h2 = i2 % 100;
        float2 wv = *reinterpret_cast<const float2*>(w + l * H + 2 * h2);
        float2 sq; sq.x = wv.x * wv.x; sq.y = wv.y * wv.y;
        *reinterpret_cast<float2*>(W2 + l * WST + 2 * h2) = sq;
    }
    __syncthreads();

    const int tx = tid & 3;        // l group: l = tx*5 + il
    const int ty = tid >> 2;       // s = s0 + ty

    const ull* Ap = reinterpret_cast<const ull*>(V1 + ty * HP);
    const ull* Bp = reinterpret_cast<const ull*>(V2);
    const ull* Wp[5];
    #pragma unroll
    for (int il = 0; il < 5; il++)
        Wp[il] = reinterpret_cast<const ull*>(W2 + (tx * 5 + il) * WST);

    ull dacc[5], naa[5], nbb[5];
    #pragma unroll
    for (int il = 0; il < 5; il++) { dacc[il] = 0ull; naa[il] = 0ull; nbb[il] = 0ull; }

    #pragma unroll 2
    for (int h2 = 0; h2 < 100; h2++) {
        ull a = Ap[h2], bb = Bp[h2];
        ull u1 = mul2(a, bb), u2 = mul2(a, a), u3 = mul2(bb, bb);
        #pragma unroll
        for (int il = 0; il < 5; il++) {
            ull wv = Wp[il][h2];
            fma2(dacc[il], u1, wv);
            fma2(naa[il], u2, wv);
            fma2(nbb[il], u3, wv);
        }
    }

    const int col = dir * 80;
    float* obase = out + (size_t)side * PSIZE + (size_t)b * S * MV;
    #pragma unroll
    for (int il = 0; il < 5; il++) {
        float d = sqrtf(red2(naa[il])) * sqrtf(red2(nbb[il]));
        obase[(s0 + ty) * MV + col + (tx * 5 + il)] = red2(dacc[il]) / fmaxf(d, EPSV);
    }
}

// ================ Kernel B2: att mean/max mp_match (kinds 1,2) ===============
// grid (B, 8, 2): y = side*4 + (kind-1)*2 + dir, z = s-half.
__global__ void __launch_bounds__(128)
match_att_kernel(const float* __restrict__ con_p,
                 const float* __restrict__ con_h,
                 const float* __restrict__ w5, const float* __restrict__ w6,
                 const float* __restrict__ w7, const float* __restrict__ w8,
                 float* __restrict__ out) {
    extern __shared__ float sm[];
    float* V1 = sm;                 // 32*HP
    float* V2 = V1 + 32 * HP;       // 32*HP
    float* W2 = V2 + 32 * HP;       // L*WST

    const int b = blockIdx.x;
    const int side = blockIdx.y >> 2;
    const int kind = 1 + ((blockIdx.y >> 1) & 1);
    const int dir = blockIdx.y & 1;
    const int shalf = blockIdx.z;
    const int tid = threadIdx.x;
    const int s0 = shalf * 32;

    const float* v1 = (side == 0 ? con_p : con_h) + (size_t)b * S * CS + dir * H;
    for (int i2 = tid; i2 < 32 * 100; i2 += 128) {
        int s = i2 / 100, h2 = i2 % 100;
        *reinterpret_cast<float2*>(V1 + s * HP + 2 * h2) =
            *reinterpret_cast<const float2*>(v1 + (s0 + s) * CS + 2 * h2);
    }
    const float* v2 = (kind == 1 ? (side == 0 ? g_amean_h : g_amean_p)
                                 : (side == 0 ? g_amax_h  : g_amax_p))
                    + (size_t)(dir * B + b) * S * H;
    for (int i2 = tid; i2 < 32 * 100; i2 += 128) {
        int s = i2 / 100, h2 = i2 % 100;
        *reinterpret_cast<float2*>(V2 + s * HP + 2 * h2) =
            *reinterpret_cast<const float2*>(v2 + (s0 + s) * H + 2 * h2);
    }

    const float* w = (kind == 1 ? (dir == 0 ? w5 : w6) : (dir == 0 ? w7 : w8));
    for (int i2 = tid; i2 < L * 100; i2 += 128) {
        int l = i2 / 100, h2 = i2 % 100;
        float2 wv = *reinterpret_cast<const float2*>(w + l * H + 2 * h2);
        float2 sq; sq.x = wv.x * wv.x; sq.y = wv.y * wv.y;
        *reinterpret_cast<float2*>(W2 + l * WST + 2 * h2) = sq;
    }
    __syncthreads();

    const int tx = tid & 3;
    const int ty = tid >> 2;

    const ull* Ap = reinterpret_cast<const ull*>(V1 + ty * HP);
    const ull* Bp = reinterpret_cast<const ull*>(V2 + ty * HP);
    const ull* Wp[5];
    #pragma unroll
    for (int il = 0; il < 5; il++)
        Wp[il] = reinterpret_cast<const ull*>(W2 + (tx * 5 + il) * WST);

    ull dacc[5], naa[5], nbb[5];
    #pragma unroll
    for (int il = 0; il < 5; il++) { dacc[il] = 0ull; naa[il] = 0ull; nbb[il] = 0ull; }

    #pragma unroll 2
    for (int h2 = 0; h2 < 100; h2++) {
        ull a = Ap[h2], bb = Bp[h2];
        ull u1 = mul2(a, bb), u2 = mul2(a, a), u3 = mul2(bb, bb);
        #pragma unroll
        for (int il = 0; il < 5; il++) {
            ull wv = Wp[il][h2];
            fma2(dacc[il], u1, wv);
            fma2(naa[il], u2, wv);
            fma2(nbb[il], u3, wv);
        }
    }

    const int col = (kind == 1 ? 40 : 60) + dir * 80;
    float* obase = out + (size_t)side * PSIZE + (size_t)b * S * MV;
    #pragma unroll
    for (int il = 0; il < 5; il++) {
        float d = sqrtf(red2(naa[il])) * sqrtf(red2(nbb[il]));
        obase[(s0 + ty) * MV + col + (tx * 5 + il)] = red2(dacc[il]) / fmaxf(d, EPSV);
    }
}

// ================= Kernel C: pairwise mp + max reductions ====================
// grid (B, 10, 2): one block per (b, l-pair, dir). 256 threads, 4x4 (p,q) tile,
// RAW P/H in smem (l-independent) + per-l w^2 broadcast: D_l = sum w^2 * p * h.
__global__ void __launch_bounds__(256, 2)
pairwise_kernel(const float* __restrict__ con_p,
                const float* __restrict__ con_h,
                const float* __restrict__ w3,
                const float* __restrict__ w4,
                float* __restrict__ out) {
    extern __shared__ float sm[];
    float* P    = sm;                 // S*HP (raw p rows)
    float* Hm   = P  + S * HP;        // S*HP (raw h rows)
    float* W2   = Hm + S * HP;        // 2*HP (w^2 for the 2 perspectives)
    float* na   = W2 + 2 * HP;        // 2*S
    float* nb   = na + 2 * S;         // 2*S
    float* redQ = nb + 2 * S;         // 2*S*8

    const int b = blockIdx.x, lg = blockIdx.y, dir = blockIdx.z;
    const int l0 = lg * 2;
    const int tid = threadIdx.x;

    const float* w = (dir == 0 ? w3 : w4) + l0 * H;
    for (int i2 = tid; i2 < 2 * 100; i2 += 256) {
        int lr = i2 / 100, h2 = i2 % 100;
        float2 wv = *reinterpret_cast<const float2*>(w + lr * H + 2 * h2);
        float2 sq; sq.x = wv.x * wv.x; sq.y = wv.y * wv.y;
        *reinterpret_cast<float2*>(W2 + lr * HP + 2 * h2) = sq;
    }

    const float* pb = con_p + (size_t)b * S * CS + dir * H;
    const float* hb = con_h + (size_t)b * S * CS + dir * H;
    for (int i2 = tid; i2 < S * 100; i2 += 256) {
        int s = i2 / 100, h2 = i2 % 100;
        *reinterpret_cast<float2*>(P  + s * HP + 2 * h2) =
            *reinterpret_cast<const float2*>(pb + s * CS + 2 * h2);
        *reinterpret_cast<float2*>(Hm + s * HP + 2 * h2) =
            *reinterpret_cast<const float2*>(hb + s * CS + 2 * h2);
    }
    __syncthreads();

    // norms: 128 threads -> (row, lr) for a-side, 128 for b-side
    {
        int t = tid & 127;
        int row = t >> 1, lr = t & 1;
        const float* src = (tid < 128) ? (P + row * HP) : (Hm + row * HP);
        const float* wr  = W2 + lr * HP;
        float acc = 0.f;
        #pragma unroll 4
        for (int k = 0; k < 100; k++) {
            float2 v = *reinterpret_cast<const float2*>(src + 2 * k);
            float2 q = *reinterpret_cast<const float2*>(wr + 2 * k);
            acc += q.x * v.x * v.x + q.y * v.y * v.y;
        }
        if (tid < 128) na[lr * S + row] = sqrtf(acc);
        else           nb[lr * S + row] = sqrtf(acc);
    }
    __syncthreads();

    const int tx = tid & 15, ty = tid >> 4;
    const int lane = tid & 31, warp = tid >> 5;
    const ull* Ap[4]; const ull* Bp[4];
    #pragma unroll
    for (int i = 0; i < 4; i++) Ap[i] = reinterpret_cast<const ull*>(P  + (ty + 16 * i) * HP);
    #pragma unroll
    for (int j = 0; j < 4; j++) Bp[j] = reinterpret_cast<const ull*>(Hm + (tx + 16 * j) * HP);
    const ull* W0 = reinterpret_cast<const ull*>(W2);
    const ull* W1 = reinterpret_cast<const ull*>(W2 + HP);

    ull acc2[2][4][4];
    #pragma unroll
    for (int lr = 0; lr < 2; lr++)
        #pragma unroll
        for (int i = 0; i < 4; i++)
            #pragma unroll
            for (int j = 0; j < 4; j++) acc2[lr][i][j] = 0ull;

    #pragma unroll 2
    for (int h2 = 0; h2 < 100; h2++) {
        ull pa[4], hbv[4];
        #pragma unroll
        for (int i = 0; i < 4; i++) pa[i] = Ap[i][h2];
        #pragma unroll
        for (int j = 0; j < 4; j++) hbv[j] = Bp[j][h2];
        ull w20 = W0[h2], w21 = W1[h2];
        ull sa[4];
        #pragma unroll
        for (int i = 0; i < 4; i++) sa[i] = mul2(pa[i], w20);
        #pragma unroll
        for (int i = 0; i < 4; i++)
            #pragma unroll
            for (int j = 0; j < 4; j++) fma2(acc2[0][i][j], sa[i], hbv[j]);
        #pragma unroll
        for (int i = 0; i < 4; i++) sa[i] = mul2(pa[i], w21);
        #pragma unroll
        for (int i = 0; i < 4; i++)
            #pragma unroll
            for (int j = 0; j < 4; j++) fma2(acc2[1][i][j], sa[i], hbv[j]);
    }

    #pragma unroll
    for (int lr = 0; lr < 2; lr++) {
        float pmax[4], qmax[4];
        #pragma unroll
        for (int i = 0; i < 4; i++) pmax[i] = -INFINITY;
        #pragma unroll
        for (int j = 0; j < 4; j++) qmax[j] = -INFINITY;

        #pragma unroll
        for (int i = 0; i < 4; i++) {
            int p = ty + 16 * i;
            #pragma unroll
            for (int j = 0; j < 4; j++) {
                int q = tx + 16 * j;
                float d = na[lr * S + p] * nb[lr * S + q];
                float c = red2(acc2[lr][i][j]) / (d > EPSV ? d : EPSV);
                pmax[i] = fmaxf(pmax[i], c);
                qmax[j] = fmaxf(qmax[j], c);
            }
        }
        const int colbase = (dir == 0 ? 20 : 100) + l0 + lr;
        #pragma unroll
        for (int m = 1; m <= 8; m <<= 1)
            #pragma unroll
            for (int i = 0; i < 4; i++)
                pmax[i] = fmaxf(pmax[i], __shfl_xor_sync(0xffffffffu, pmax[i], m));
        if (tx == 0) {
            #pragma unroll
            for (int i = 0; i < 4; i++)
                out[((size_t)b * S + (ty + 16 * i)) * MV + colbase] = pmax[i]; // mv_p
        }
        #pragma unroll
        for (int j = 0; j < 4; j++)
            qmax[j] = fmaxf(qmax[j], __shfl_xor_sync(0xffffffffu, qmax[j], 16));
        if (lane < 16) {
            #pragma unroll
            for (int j = 0; j < 4; j++)
                redQ[(lr * S + tx + 16 * j) * 8 + warp] = qmax[j];
        }
    }
    __syncthreads();
    if (tid < 128) {
        int lr = tid >> 6, q = tid & 63;
        float m = -INFINITY;
        #pragma unroll
        for (int k = 0; k < 8; k++) m = fmaxf(m, redQ[(lr * S + q) * 8 + k]);
        const int colbase = (dir == 0 ? 20 : 100) + l0 + lr;
        out[(size_t)PSIZE + ((size_t)b * S + q) * MV + colbase] = m;          // mv_h
    }
}

// ================================ launcher ===================================
extern "C" void kernel_launch(void* const* d_in, const int* in_sizes, int n_in,
                              void* d_out, int out_size) {
    const float* con_p = (const float*)d_in[0];
    const float* con_h = (const float*)d_in[1];
    const float* w1 = (const float*)d_in[2];
    const float* w2 = (const float*)d_in[3];
    const float* w3 = (const float*)d_in[4];
    const float* w4 = (const float*)d_in[5];
    const float* w5 = (const float*)d_in[6];
    const float* w6 = (const float*)d_in[7];
    const float* w7 = (const float*)d_in[8];
    const float* w8 = (const float*)d_in[9];
    float* out = (float*)d_out;

    constexpr size_t SM_A1 = (size_t)(2 * S * HP + 2 * S + S * 8) * sizeof(float);
    constexpr size_t SM_A2 = (size_t)(2 * S * AST + S * VST + S) * sizeof(float);
    constexpr size_t SM_BF = (size_t)(32 * HP + HP + L * WST) * sizeof(float);
    constexpr size_t SM_BA = (size_t)(2 * 32 * HP + L * WST) * sizeof(float);
    constexpr size_t SM_C  = (size_t)(2 * S * HP + 2 * HP + 4 * S + 2 * S * 8) * sizeof(float);

    static cudaStream_t s2 = nullptr;
    static cudaEvent_t evFork = nullptr, evJoin = nullptr;
    static bool init_done = false;
    if (!init_done) {
        cudaFuncSetAttribute(attn_kernel,       cudaFuncAttributeMaxDynamicSharedMemorySize, (int)SM_A1);
        cudaFuncSetAttribute(attderiv_kernel,   cudaFuncAttributeMaxDynamicSharedMemorySize, (int)SM_A2);
        cudaFuncSetAttribute(match_full_kernel, cudaFuncAttributeMaxDynamicSharedMemorySize, (int)SM_BF);
        cudaFuncSetAttribute(match_att_kernel,  cudaFuncAttributeMaxDynamicSharedMemorySize, (int)SM_BA);
        cudaFuncSetAttribute(pairwise_kernel,   cudaFuncAttributeMaxDynamicSharedMemorySize, (int)SM_C);
        cudaStreamCreateWithFlags(&s2, cudaStreamNonBlocking);
        cudaEventCreateWithFlags(&evFork, cudaEventDisableTiming);
        cudaEventCreateWithFlags(&evJoin, cudaEventDisableTiming);
        init_done = true;
    }

    // Fork: pairwise (cols 20-39/100-119) on s2; chain on stream 0.
    cudaEventRecord(evFork, 0);
    cudaStreamWaitEvent(s2, evFork, 0);
    pairwise_kernel<<<dim3(B, 10, 2), 256, SM_C, s2>>>(con_p, con_h, w3, w4, out);

    attn_kernel<<<dim3(B, 2), 256, SM_A1>>>(con_p, con_h);
    match_full_kernel<<<dim3(B, 4, 2), 128, SM_BF>>>(con_p, con_h, w1, w2, out);
    attderiv_kernel<<<dim3(B, 2, 4), 256, SM_A2>>>(con_p, con_h);
    match_att_kernel<<<dim3(B, 8, 2), 128, SM_BA>>>(con_p, con_h, w5, w6, w7, w8, out);

    cudaEventRecord(evJoin, s2);
    cudaStreamWaitEvent(0, evJoin, 0);
}

// round 8
// speedup vs baseline: 1.0320x; 1.0159x over previous
#include <cuda_runtime.h>
#include <math.h>

#define EPSV 1e-8f

typedef unsigned long long ull;

namespace {
constexpr int B  = 32;
constexpr int S  = 64;
constexpr int H  = 200;
constexpr int L  = 20;
constexpr int HP = 202;      // smem row stride (101 ull; 101%16=5 -> conflict-free)
constexpr int CS = 400;      // con_* inner stride (2*H)
constexpr int MV = 160;      // 8*L output columns
constexpr int PSIZE = B * S * MV;
constexpr int AST = 66;      // att/attT row stride in fused kernel
constexpr int WST = 200;     // match W2 row stride
}

// packed f32x2 helpers (ptxas never auto-fuses these)
__device__ __forceinline__ void fma2(ull& d, ull a, ull b) {
    asm("fma.rn.f32x2 %0, %1, %2, %0;" : "+l"(d) : "l"(a), "l"(b));
}
__device__ __forceinline__ ull mul2(ull a, ull b) {
    ull r; asm("mul.rn.f32x2 %0, %1, %2;" : "=l"(r) : "l"(a), "l"(b)); return r;
}
__device__ __forceinline__ float red2(ull v) {
    float2 f = *reinterpret_cast<float2*>(&v);
    return f.x + f.y;
}

// ---------------- scratch (device globals; no allocation allowed) -------------
__device__ __align__(16) float g_amean_h[2 * B * S * H];
__device__ __align__(16) float g_amax_h [2 * B * S * H];
__device__ __align__(16) float g_amean_p[2 * B * S * H];
__device__ __align__(16) float g_amax_p [2 * B * S * H];

// =============== Kernel A: fused attention + att mean/max vectors ============
// grid (B, 2), 256 threads. Computes cosine att (4x4 tile GEMM), row/col sums,
// then the mean/max attention-weighted vectors for BOTH sides, all from smem.
__global__ void __launch_bounds__(256)
attnderiv_kernel(const float* __restrict__ con_p,
                 const float* __restrict__ con_h) {
    extern __shared__ float sm[];
    float* P     = sm;                 // S*HP  (raw p rows)
    float* Hm    = P  + S * HP;        // S*HP  (raw h rows)
    float* att   = Hm + S * HP;        // S*AST (att[p][q])
    float* attT  = att + S * AST;      // S*AST (att[q][p])
    float* np    = attT + S * AST;     // S
    float* nh    = np + S;             // S
    float* rsumS = nh + S;             // S
    float* csumS = rsumS + S;          // S
    float* redCS = csumS + S;          // S*8

    const int b = blockIdx.x, dir = blockIdx.y;
    const int tid = threadIdx.x;
    const float* pbase = con_p + (size_t)b * S * CS + dir * H;
    const float* hbase = con_h + (size_t)b * S * CS + dir * H;

    for (int i2 = tid; i2 < S * 100; i2 += 256) {
        int s = i2 / 100, h2 = i2 % 100;
        *reinterpret_cast<float2*>(P  + s * HP + 2 * h2) =
            *reinterpret_cast<const float2*>(pbase + s * CS + 2 * h2);
        *reinterpret_cast<float2*>(Hm + s * HP + 2 * h2) =
            *reinterpret_cast<const float2*>(hbase + s * CS + 2 * h2);
    }
    __syncthreads();

    if (tid < 64) {
        float acc = 0.f;
        #pragma unroll 4
        for (int k = 0; k < 100; k++) {
            float2 v = *reinterpret_cast<const float2*>(P + tid * HP + 2 * k);
            acc += v.x * v.x + v.y * v.y;
        }
        np[tid] = sqrtf(acc);
    } else if (tid < 128) {
        int q = tid - 64;
        float acc = 0.f;
        #pragma unroll 4
        for (int k = 0; k < 100; k++) {
            float2 v = *reinterpret_cast<const float2*>(Hm + q * HP + 2 * k);
            acc += v.x * v.x + v.y * v.y;
        }
        nh[q] = sqrtf(acc);
    }
    __syncthreads();

    // ---- att GEMM (4x4 tile, f32x2 packed) ----
    {
        const int tx = tid & 15, ty = tid >> 4;
        const int lane = tid & 31, warp = tid >> 5;
        const ull* Ap[4]; const ull* Bp[4];
        #pragma unroll
        for (int i = 0; i < 4; i++) Ap[i] = reinterpret_cast<const ull*>(P  + (ty + 16 * i) * HP);
        #pragma unroll
        for (int j = 0; j < 4; j++) Bp[j] = reinterpret_cast<const ull*>(Hm + (tx + 16 * j) * HP);

        ull acc2[4][4];
        #pragma unroll
        for (int i = 0; i < 4; i++)
            #pragma unroll
            for (int j = 0; j < 4; j++) acc2[i][j] = 0ull;

        ull ca[4], cb[4];
        #pragma unroll
        for (int i = 0; i < 4; i++) ca[i] = Ap[i][0];
        #pragma unroll
        for (int j = 0; j < 4; j++) cb[j] = Bp[j][0];

        #pragma unroll 2
        for (int h2 = 1; h2 < 100; h2++) {
            ull ta[4], tb[4];
            #pragma unroll
            for (int i = 0; i < 4; i++) ta[i] = Ap[i][h2];
            #pragma unroll
            for (int j = 0; j < 4; j++) tb[j] = Bp[j][h2];
            #pragma unroll
            for (int i = 0; i < 4; i++)
                #pragma unroll
                for (int j = 0; j < 4; j++) fma2(acc2[i][j], ca[i], cb[j]);
            #pragma unroll
            for (int i = 0; i < 4; i++) ca[i] = ta[i];
            #pragma unroll
            for (int j = 0; j < 4; j++) cb[j] = tb[j];
        }
        #pragma unroll
        for (int i = 0; i < 4; i++)
            #pragma unroll
            for (int j = 0; j < 4; j++) fma2(acc2[i][j], ca[i], cb[j]);

        float rsum[4], csum[4];
        #pragma unroll
        for (int i = 0; i < 4; i++) rsum[i] = 0.f;
        #pragma unroll
        for (int j = 0; j < 4; j++) csum[j] = 0.f;

        #pragma unroll
        for (int i = 0; i < 4; i++) {
            int p = ty + 16 * i;
            #pragma unroll
            for (int j = 0; j < 4; j++) {
                int q = tx + 16 * j;
                float d = np[p] * nh[q];
                float c = red2(acc2[i][j]) / (d > EPSV ? d : EPSV);
                att [p * AST + q] = c;
                attT[q * AST + p] = c;
                rsum[i] += c;
                csum[j] += c;
            }
        }
        #pragma unroll
        for (int m = 1; m <= 8; m <<= 1)
            #pragma unroll
            for (int i = 0; i < 4; i++)
                rsum[i] += __shfl_xor_sync(0xffffffffu, rsum[i], m);
        if (tx == 0) {
            #pragma unroll
            for (int i = 0; i < 4; i++)
                rsumS[ty + 16 * i] = rsum[i];
        }
        #pragma unroll
        for (int j = 0; j < 4; j++)
            csum[j] += __shfl_xor_sync(0xffffffffu, csum[j], 16);
        if (lane < 16) {
            #pragma unroll
            for (int j = 0; j < 4; j++)
                redCS[(tx + 16 * j) * 8 + warp] = csum[j];
        }
    }
    __syncthreads();
    if (tid < 64) {
        float s0 = 0.f;
        #pragma unroll
        for (int k = 0; k < 8; k++) s0 += redCS[tid * 8 + k];
        csumS[tid] = s0;
    }
    __syncthreads();

    // ---- deriv phase: mean/max over the att axis, both sides, from smem ----
    if (tid < 200) {
        const int oi = tid / 25, hi = tid % 25;
        const int o0 = oi * 8;

        for (int side = 0; side < 2; side++) {
            const float* M  = (side == 0) ? att : attT;   // M[o][*]
            const float* V  = (side == 0) ? Hm  : P;      // V[*][h], stride HP
            const float* ds = (side == 0) ? rsumS : csumS;
            float* gmean = (side == 0 ? g_amean_h : g_amean_p)
                         + (size_t)(dir * B + b) * S * H;
            float* gmax  = (side == 0 ? g_amax_h  : g_amax_p )
                         + (size_t)(dir * B + b) * S * H;

            for (int ck = 0; ck < 2; ck++) {
                const int hb = ck * 100 + hi * 4;

                float ss[8][4], sx[8][4];
                #pragma unroll
                for (int io = 0; io < 8; io++)
                    #pragma unroll
                    for (int k = 0; k < 4; k++) { ss[io][k] = 0.f; sx[io][k] = -INFINITY; }

                for (int q2 = 0; q2 < 32; q2++) {
                    const int q = 2 * q2;
                    float2 av[8];
                    #pragma unroll
                    for (int io = 0; io < 8; io++)
                        av[io] = *reinterpret_cast<const float2*>(M + (o0 + io) * AST + q);
                    float2 va0 = *reinterpret_cast<const float2*>(V + q * HP + hb);
                    float2 va1 = *reinterpret_cast<const float2*>(V + q * HP + hb + 2);
                    float2 vb0 = *reinterpret_cast<const float2*>(V + (q + 1) * HP + hb);
                    float2 vb1 = *reinterpret_cast<const float2*>(V + (q + 1) * HP + hb + 2);
                    float vv0[4] = {va0.x, va0.y, va1.x, va1.y};
                    float vv1[4] = {vb0.x, vb0.y, vb1.x, vb1.y};
                    #pragma unroll
                    for (int io = 0; io < 8; io++) {
                        float ax = av[io].x, ay = av[io].y;
                        #pragma unroll
                        for (int k = 0; k < 4; k++) {
                            float t0 = ax * vv0[k];
                            float t1 = ay * vv1[k];
                            ss[io][k] += t0 + t1;
                            sx[io][k] = fmaxf(sx[io][k], fmaxf(t0, t1));
                        }
                    }
                }
                #pragma unroll
                for (int io = 0; io < 8; io++) {
                    float d = ds[o0 + io];
                    float inv = 1.f / (d > EPSV ? d : EPSV);
                    float4 m4, x4;
                    m4.x = ss[io][0] * inv; m4.y = ss[io][1] * inv;
                    m4.z = ss[io][2] * inv; m4.w = ss[io][3] * inv;
                    x4.x = sx[io][0]; x4.y = sx[io][1]; x4.z = sx[io][2]; x4.w = sx[io][3];
                    *reinterpret_cast<float4*>(gmean + (o0 + io) * H + hb) = m4;
                    *reinterpret_cast<float4*>(gmax  + (o0 + io) * H + hb) = x4;
                }
            }
        }
    }
}

// ================== Kernel B1: "full" mp_match (kind 0) =====================
// grid (B, 4, 2): y = side*2 + dir, z = s-half. Independent of attention.
__global__ void __launch_bounds__(128)
match_full_kernel(const float* __restrict__ con_p,
                  const float* __restrict__ con_h,
                  const float* __restrict__ w1, const float* __restrict__ w2,
                  float* __restrict__ out) {
    extern __shared__ float sm[];
    float* V1 = sm;                 // 32*HP
    float* V2 = V1 + 32 * HP;       // HP (single row)
    float* W2 = V2 + HP;            // L*WST

    const int b = blockIdx.x;
    const int side = blockIdx.y >> 1;
    const int dir = blockIdx.y & 1;
    const int shalf = blockIdx.z;
    const int tid = threadIdx.x;
    const int s0 = shalf * 32;

    const float* v1 = (side == 0 ? con_p : con_h) + (size_t)b * S * CS + dir * H;
    for (int i2 = tid; i2 < 32 * 100; i2 += 128) {
        int s = i2 / 100, h2 = i2 % 100;
        *reinterpret_cast<float2*>(V1 + s * HP + 2 * h2) =
            *reinterpret_cast<const float2*>(v1 + (s0 + s) * CS + 2 * h2);
    }
    const float* v2 = (side == 0 ? con_h : con_p)
                    + (size_t)b * S * CS + (dir == 0 ? (S - 1) : 0) * CS + dir * H;
    for (int h2 = tid; h2 < 100; h2 += 128)
        *reinterpret_cast<float2*>(V2 + 2 * h2) =
            *reinterpret_cast<const float2*>(v2 + 2 * h2);

    const float* w = (dir == 0 ? w1 : w2);
    for (int i2 = tid; i2 < L * 100; i2 += 128) {
        int l = i2 / 100, h2 = i2 % 100;
        float2 wv = *reinterpret_cast<const float2*>(w + l * H + 2 * h2);
        float2 sq; sq.x = wv.x * wv.x; sq.y = wv.y * wv.y;
        *reinterpret_cast<float2*>(W2 + l * WST + 2 * h2) = sq;
    }
    __syncthreads();

    const int tx = tid & 3;        // l group: l = tx*5 + il
    const int ty = tid >> 2;       // s = s0 + ty

    const ull* Ap = reinterpret_cast<const ull*>(V1 + ty * HP);
    const ull* Bp = reinterpret_cast<const ull*>(V2);
    const ull* Wp[5];
    #pragma unroll
    for (int il = 0; il < 5; il++)
        Wp[il] = reinterpret_cast<const ull*>(W2 + (tx * 5 + il) * WST);

    ull dacc[5], naa[5], nbb[5];
    #pragma unroll
    for (int il = 0; il < 5; il++) { dacc[il] = 0ull; naa[il] = 0ull; nbb[il] = 0ull; }

    #pragma unroll 2
    for (int h2 = 0; h2 < 100; h2++) {
        ull a = Ap[h2], bb = Bp[h2];
        ull u1 = mul2(a, bb), u2 = mul2(a, a), u3 = mul2(bb, bb);
        #pragma unroll
        for (int il = 0; il < 5; il++) {
            ull wv = Wp[il][h2];
            fma2(dacc[il], u1, wv);
            fma2(naa[il], u2, wv);
            fma2(nbb[il], u3, wv);
        }
    }

    const int col = dir * 80;
    float* obase = out + (size_t)side * PSIZE + (size_t)b * S * MV;
    #pragma unroll
    for (int il = 0; il < 5; il++) {
        float d = sqrtf(red2(naa[il])) * sqrtf(red2(nbb[il]));
        obase[(s0 + ty) * MV + col + (tx * 5 + il)] = red2(dacc[il]) / fmaxf(d, EPSV);
    }
}

// ================ Kernel B2: att mean/max mp_match (kinds 1,2) ===============
// grid (B, 8, 2): y = side*4 + (kind-1)*2 + dir, z = s-half.
__global__ void __launch_bounds__(128)
match_att_kernel(const float* __restrict__ con_p,
                 const float* __restrict__ con_h,
                 const float* __restrict__ w5, const float* __restrict__ w6,
                 const float* __restrict__ w7, const float* __restrict__ w8,
                 float* __restrict__ out) {
    extern __shared__ float sm[];
    float* V1 = sm;                 // 32*HP
    float* V2 = V1 + 32 * HP;       // 32*HP
    float* W2 = V2 + 32 * HP;       // L*WST

    const int b = blockIdx.x;
    const int side = blockIdx.y >> 2;
    const int kind = 1 + ((blockIdx.y >> 1) & 1);
    const int dir = blockIdx.y & 1;
    const int shalf = blockIdx.z;
    const int tid = threadIdx.x;
    const int s0 = shalf * 32;

    const float* v1 = (side == 0 ? con_p : con_h) + (size_t)b * S * CS + dir * H;
    for (int i2 = tid; i2 < 32 * 100; i2 += 128) {
        int s = i2 / 100, h2 = i2 % 100;
        *reinterpret_cast<float2*>(V1 + s * HP + 2 * h2) =
            *reinterpret_cast<const float2*>(v1 + (s0 + s) * CS + 2 * h2);
    }
    const float* v2 = (kind == 1 ? (side == 0 ? g_amean_h : g_amean_p)
                                 : (side == 0 ? g_amax_h  : g_amax_p))
                    + (size_t)(dir * B + b) * S * H;
    for (int i2 = tid; i2 < 32 * 100; i2 += 128) {
        int s = i2 / 100, h2 = i2 % 100;
        *reinterpret_cast<float2*>(V2 + s * HP + 2 * h2) =
            *reinterpret_cast<const float2*>(v2 + (s0 + s) * H + 2 * h2);
    }

    const float* w = (kind == 1 ? (dir == 0 ? w5 : w6) : (dir == 0 ? w7 : w8));
    for (int i2 = tid; i2 < L * 100; i2 += 128) {
        int l = i2 / 100, h2 = i2 % 100;
        float2 wv = *reinterpret_cast<const float2*>(w + l * H + 2 * h2);
        float2 sq; sq.x = wv.x * wv.x; sq.y = wv.y * wv.y;
        *reinterpret_cast<float2*>(W2 + l * WST + 2 * h2) = sq;
    }
    __syncthreads();

    const int tx = tid & 3;
    const int ty = tid >> 2;

    const ull* Ap = reinterpret_cast<const ull*>(V1 + ty * HP);
    const ull* Bp = reinterpret_cast<const ull*>(V2 + ty * HP);
    const ull* Wp[5];
    #pragma unroll
    for (int il = 0; il < 5; il++)
        Wp[il] = reinterpret_cast<const ull*>(W2 + (tx * 5 + il) * WST);

    ull dacc[5], naa[5], nbb[5];
    #pragma unroll
    for (int il = 0; il < 5; il++) { dacc[il] = 0ull; naa[il] = 0ull; nbb[il] = 0ull; }

    #pragma unroll 2
    for (int h2 = 0; h2 < 100; h2++) {
        ull a = Ap[h2], bb = Bp[h2];
        ull u1 = mul2(a, bb), u2 = mul2(a, a), u3 = mul2(bb, bb);
        #pragma unroll
        for (int il = 0; il < 5; il++) {
            ull wv = Wp[il][h2];
            fma2(dacc[il], u1, wv);
            fma2(naa[il], u2, wv);
            fma2(nbb[il], u3, wv);
        }
    }

    const int col = (kind == 1 ? 40 : 60) + dir * 80;
    float* obase = out + (size_t)side * PSIZE + (size_t)b * S * MV;
    #pragma unroll
    for (int il = 0; il < 5; il++) {
        float d = sqrtf(red2(naa[il])) * sqrtf(red2(nbb[il]));
        obase[(s0 + ty) * MV + col + (tx * 5 + il)] = red2(dacc[il]) / fmaxf(d, EPSV);
    }
}

// ================= Kernel C: pairwise mp + max reductions ====================
// grid (B, 10, 2): one block per (b, l-pair, dir). 256 threads, 4x4 (p,q) tile,
// RAW P/H in smem (l-independent) + per-l w^2 broadcast: D_l = sum w^2 * p * h.
__global__ void __launch_bounds__(256, 2)
pairwise_kernel(const float* __restrict__ con_p,
                const float* __restrict__ con_h,
                const float* __restrict__ w3,
                const float* __restrict__ w4,
                float* __restrict__ out) {
    extern __shared__ float sm[];
    float* P    = sm;                 // S*HP (raw p rows)
    float* Hm   = P  + S * HP;        // S*HP (raw h rows)
    float* W2   = Hm + S * HP;        // 2*HP (w^2 for the 2 perspectives)
    float* na   = W2 + 2 * HP;        // 2*S
    float* nb   = na + 2 * S;         // 2*S
    float* redQ = nb + 2 * S;         // 2*S*8

    const int b = blockIdx.x, lg = blockIdx.y, dir = blockIdx.z;
    const int l0 = lg * 2;
    const int tid = threadIdx.x;

    const float* w = (dir == 0 ? w3 : w4) + l0 * H;
    for (int i2 = tid; i2 < 2 * 100; i2 += 256) {
        int lr = i2 / 100, h2 = i2 % 100;
        float2 wv = *reinterpret_cast<const float2*>(w + lr * H + 2 * h2);
        float2 sq; sq.x = wv.x * wv.x; sq.y = wv.y * wv.y;
        *reinterpret_cast<float2*>(W2 + lr * HP + 2 * h2) = sq;
    }

    const float* pb = con_p + (size_t)b * S * CS + dir * H;
    const float* hb = con_h + (size_t)b * S * CS + dir * H;
    for (int i2 = tid; i2 < S * 100; i2 += 256) {
        int s = i2 / 100, h2 = i2 % 100;
        *reinterpret_cast<float2*>(P  + s * HP + 2 * h2) =
            *reinterpret_cast<const float2*>(pb + s * CS + 2 * h2);
        *reinterpret_cast<float2*>(Hm + s * HP + 2 * h2) =
            *reinterpret_cast<const float2*>(hb + s * CS + 2 * h2);
    }
    __syncthreads();

    // norms: 128 threads -> (row, lr) for a-side, 128 for b-side
    {
        int t = tid & 127;
        int row = t >> 1, lr = t & 1;
        const float* src = (tid < 128) ? (P + row * HP) : (Hm + row * HP);
        const float* wr  = W2 + lr * HP;
        float acc = 0.f;
        #pragma unroll 4
        for (int k = 0; k < 100; k++) {
            float2 v = *reinterpret_cast<const float2*>(src + 2 * k);
            float2 q = *reinterpret_cast<const float2*>(wr + 2 * k);
            acc += q.x * v.x * v.x + q.y * v.y * v.y;
        }
        if (tid < 128) na[lr * S + row] = sqrtf(acc);
        else           nb[lr * S + row] = sqrtf(acc);
    }
    __syncthreads();

    const int tx = tid & 15, ty = tid >> 4;
    const int lane = tid & 31, warp = tid >> 5;
    const ull* Ap[4]; const ull* Bp[4];
    #pragma unroll
    for (int i = 0; i < 4; i++) Ap[i] = reinterpret_cast<const ull*>(P  + (ty + 16 * i) * HP);
    #pragma unroll
    for (int j = 0; j < 4; j++) Bp[j] = reinterpret_cast<const ull*>(Hm + (tx + 16 * j) * HP);
    const ull* W0 = reinterpret_cast<const ull*>(W2);
    const ull* W1 = reinterpret_cast<const ull*>(W2 + HP);

    ull acc2[2][4][4];
    #pragma unroll
    for (int lr = 0; lr < 2; lr++)
        #pragma unroll
        for (int i = 0; i < 4; i++)
            #pragma unroll
            for (int j = 0; j < 4; j++) acc2[lr][i][j] = 0ull;

    #pragma unroll 2
    for (int h2 = 0; h2 < 100; h2++) {
        ull pa[4], hbv[4];
        #pragma unroll
        for (int i = 0; i < 4; i++) pa[i] = Ap[i][h2];
        #pragma unroll
        for (int j = 0; j < 4; j++) hbv[j] = Bp[j][h2];
        ull w20 = W0[h2], w21 = W1[h2];
        ull sa[4];
        #pragma unroll
        for (int i = 0; i < 4; i++) sa[i] = mul2(pa[i], w20);
        #pragma unroll
        for (int i = 0; i < 4; i++)
            #pragma unroll
            for (int j = 0; j < 4; j++) fma2(acc2[0][i][j], sa[i], hbv[j]);
        #pragma unroll
        for (int i = 0; i < 4; i++) sa[i] = mul2(pa[i], w21);
        #pragma unroll
        for (int i = 0; i < 4; i++)
            #pragma unroll
            for (int j = 0; j < 4; j++) fma2(acc2[1][i][j], sa[i], hbv[j]);
    }

    #pragma unroll
    for (int lr = 0; lr < 2; lr++) {
        float pmax[4], qmax[4];
        #pragma unroll
        for (int i = 0; i < 4; i++) pmax[i] = -INFINITY;
        #pragma unroll
        for (int j = 0; j < 4; j++) qmax[j] = -INFINITY;

        #pragma unroll
        for (int i = 0; i < 4; i++) {
            int p = ty + 16 * i;
            #pragma unroll
            for (int j = 0; j < 4; j++) {
                int q = tx + 16 * j;
                float d = na[lr * S + p] * nb[lr * S + q];
                float c = red2(acc2[lr][i][j]) / (d > EPSV ? d : EPSV);
                pmax[i] = fmaxf(pmax[i], c);
                qmax[j] = fmaxf(qmax[j], c);
            }
        }
        const int colbase = (dir == 0 ? 20 : 100) + l0 + lr;
        #pragma unroll
        for (int m = 1; m <= 8; m <<= 1)
            #pragma unroll
            for (int i = 0; i < 4; i++)
                pmax[i] = fmaxf(pmax[i], __shfl_xor_sync(0xffffffffu, pmax[i], m));
        if (tx == 0) {
            #pragma unroll
            for (int i = 0; i < 4; i++)
                out[((size_t)b * S + (ty + 16 * i)) * MV + colbase] = pmax[i]; // mv_p
        }
        #pragma unroll
        for (int j = 0; j < 4; j++)
            qmax[j] = fmaxf(qmax[j], __shfl_xor_sync(0xffffffffu, qmax[j], 16));
        if (lane < 16) {
            #pragma unroll
            for (int j = 0; j < 4; j++)
                redQ[(lr * S + tx + 16 * j) * 8 + warp] = qmax[j];
        }
    }
    __syncthreads();
    if (tid < 128) {
        int lr = tid >> 6, q = tid & 63;
        float m = -INFINITY;
        #pragma unroll
        for (int k = 0; k < 8; k++) m = fmaxf(m, redQ[(lr * S + q) * 8 + k]);
        const int colbase = (dir == 0 ? 20 : 100) + l0 + lr;
        out[(size_t)PSIZE + ((size_t)b * S + q) * MV + colbase] = m;          // mv_h
    }
}

// ================================ launcher ===================================
extern "C" void kernel_launch(void* const* d_in, const int* in_sizes, int n_in,
                              void* d_out, int out_size) {
    const float* con_p = (const float*)d_in[0];
    const float* con_h = (const float*)d_in[1];
    const float* w1 = (const float*)d_in[2];
    const float* w2 = (const float*)d_in[3];
    const float* w3 = (const float*)d_in[4];
    const float* w4 = (const float*)d_in[5];
    const float* w5 = (const float*)d_in[6];
    const float* w6 = (const float*)d_in[7];
    const float* w7 = (const float*)d_in[8];
    const float* w8 = (const float*)d_in[9];
    float* out = (float*)d_out;

    constexpr size_t SM_AD = (size_t)(2 * S * HP + 2 * S * AST + 4 * S + S * 8) * sizeof(float);
    constexpr size_t SM_BF = (size_t)(32 * HP + HP + L * WST) * sizeof(float);
    constexpr size_t SM_BA = (size_t)(2 * 32 * HP + L * WST) * sizeof(float);
    constexpr size_t SM_C  = (size_t)(2 * S * HP + 2 * HP + 4 * S + 2 * S * 8) * sizeof(float);

    static cudaStream_t s2 = nullptr;
    static cudaEvent_t evFork = nullptr, evJoin = nullptr;
    static bool init_done = false;
    if (!init_done) {
        cudaFuncSetAttribute(attnderiv_kernel,  cudaFuncAttributeMaxDynamicSharedMemorySize, (int)SM_AD);
        cudaFuncSetAttribute(match_full_kernel, cudaFuncAttributeMaxDynamicSharedMemorySize, (int)SM_BF);
        cudaFuncSetAttribute(match_att_kernel,  cudaFuncAttributeMaxDynamicSharedMemorySize, (int)SM_BA);
        cudaFuncSetAttribute(pairwise_kernel,   cudaFuncAttributeMaxDynamicSharedMemorySize, (int)SM_C);
        cudaStreamCreateWithFlags(&s2, cudaStreamNonBlocking);
        cudaEventCreateWithFlags(&evFork, cudaEventDisableTiming);
        cudaEventCreateWithFlags(&evJoin, cudaEventDisableTiming);
        init_done = true;
    }

    // s2: pairwise (out cols 20-39/100-119) then match_full (cols 0-19/80-99).
    // stream 0: fused attn+deriv -> match_att (cols 40-79/120-159).
    cudaEventRecord(evFork, 0);
    cudaStreamWaitEvent(s2, evFork, 0);
    pairwise_kernel<<<dim3(B, 10, 2), 256, SM_C, s2>>>(con_p, con_h, w3, w4, out);
    match_full_kernel<<<dim3(B, 4, 2), 128, SM_BF, s2>>>(con_p, con_h, w1, w2, out);

    attnderiv_kernel<<<dim3(B, 2), 256, SM_AD>>>(con_p, con_h);
    match_att_kernel<<<dim3(B, 8, 2), 128, SM_BA>>>(con_p, con_h, w5, w6, w7, w8, out);

    cudaEventRecord(evJoin, s2);
    cudaStreamWaitEvent(0, evJoin, 0);
}

// round 9
// speedup vs baseline: 1.1016x; 1.0674x over previous
#include <cuda_runtime.h>
#include <math.h>

#define EPSV 1e-8f

typedef unsigned long long ull;

namespace {
constexpr int B  = 32;
constexpr int S  = 64;
constexpr int H  = 200;
constexpr int L  = 20;
constexpr int HP = 202;      // smem row stride (101 ull; 101%16=5 -> conflict-free)
constexpr int CS = 400;      // con_* inner stride (2*H)
constexpr int MV = 160;      // 8*L output columns
constexpr int PSIZE = B * S * MV;
constexpr int AST = 66;      // att/attT row stride in fused kernel
constexpr int WST = 200;     // match W2 row stride
}

// packed f32x2 helpers (ptxas never auto-fuses these)
__device__ __forceinline__ void fma2(ull& d, ull a, ull b) {
    asm("fma.rn.f32x2 %0, %1, %2, %0;" : "+l"(d) : "l"(a), "l"(b));
}
__device__ __forceinline__ ull mul2(ull a, ull b) {
    ull r; asm("mul.rn.f32x2 %0, %1, %2;" : "=l"(r) : "l"(a), "l"(b)); return r;
}
__device__ __forceinline__ float red2(ull v) {
    float2 f = *reinterpret_cast<float2*>(&v);
    return f.x + f.y;
}

// ---------------- scratch (device globals; no allocation allowed) -------------
__device__ __align__(16) float g_amean_h[2 * B * S * H];
__device__ __align__(16) float g_amax_h [2 * B * S * H];
__device__ __align__(16) float g_amean_p[2 * B * S * H];
__device__ __align__(16) float g_amax_p [2 * B * S * H];

// =============== Kernel A: fused attention + att mean/max vectors ============
// grid (B, 2), 256 threads. Cosine att (4x4 tile GEMM), row/col sums, then the
// mean/max attention-weighted vectors for BOTH sides, all from smem.
__global__ void __launch_bounds__(256)
attnderiv_kernel(const float* __restrict__ con_p,
                 const float* __restrict__ con_h) {
    extern __shared__ float sm[];
    float* P     = sm;                 // S*HP  (raw p rows)
    float* Hm    = P  + S * HP;        // S*HP  (raw h rows)
    float* att   = Hm + S * HP;        // S*AST (att[p][q])
    float* attT  = att + S * AST;      // S*AST (att[q][p])
    float* np    = attT + S * AST;     // S
    float* nh    = np + S;             // S
    float* rsumS = nh + S;             // S
    float* csumS = rsumS + S;          // S
    float* redCS = csumS + S;          // S*8

    const int b = blockIdx.x, dir = blockIdx.y;
    const int tid = threadIdx.x;
    const float* pbase = con_p + (size_t)b * S * CS + dir * H;
    const float* hbase = con_h + (size_t)b * S * CS + dir * H;

    for (int i2 = tid; i2 < S * 100; i2 += 256) {
        int s = i2 / 100, h2 = i2 % 100;
        *reinterpret_cast<float2*>(P  + s * HP + 2 * h2) =
            *reinterpret_cast<const float2*>(pbase + s * CS + 2 * h2);
        *reinterpret_cast<float2*>(Hm + s * HP + 2 * h2) =
            *reinterpret_cast<const float2*>(hbase + s * CS + 2 * h2);
    }
    __syncthreads();

    if (tid < 64) {
        float acc = 0.f;
        #pragma unroll 4
        for (int k = 0; k < 100; k++) {
            float2 v = *reinterpret_cast<const float2*>(P + tid * HP + 2 * k);
            acc += v.x * v.x + v.y * v.y;
        }
        np[tid] = sqrtf(acc);
    } else if (tid < 128) {
        int q = tid - 64;
        float acc = 0.f;
        #pragma unroll 4
        for (int k = 0; k < 100; k++) {
            float2 v = *reinterpret_cast<const float2*>(Hm + q * HP + 2 * k);
            acc += v.x * v.x + v.y * v.y;
        }
        nh[q] = sqrtf(acc);
    }
    __syncthreads();

    // ---- att GEMM (4x4 tile, f32x2 packed) ----
    {
        const int tx = tid & 15, ty = tid >> 4;
        const int lane = tid & 31, warp = tid >> 5;
        const ull* Ap[4]; const ull* Bp[4];
        #pragma unroll
        for (int i = 0; i < 4; i++) Ap[i] = reinterpret_cast<const ull*>(P  + (ty + 16 * i) * HP);
        #pragma unroll
        for (int j = 0; j < 4; j++) Bp[j] = reinterpret_cast<const ull*>(Hm + (tx + 16 * j) * HP);

        ull acc2[4][4];
        #pragma unroll
        for (int i = 0; i < 4; i++)
            #pragma unroll
            for (int j = 0; j < 4; j++) acc2[i][j] = 0ull;

        ull ca[4], cb[4];
        #pragma unroll
        for (int i = 0; i < 4; i++) ca[i] = Ap[i][0];
        #pragma unroll
        for (int j = 0; j < 4; j++) cb[j] = Bp[j][0];

        #pragma unroll 2
        for (int h2 = 1; h2 < 100; h2++) {
            ull ta[4], tb[4];
            #pragma unroll
            for (int i = 0; i < 4; i++) ta[i] = Ap[i][h2];
            #pragma unroll
            for (int j = 0; j < 4; j++) tb[j] = Bp[j][h2];
            #pragma unroll
            for (int i = 0; i < 4; i++)
                #pragma unroll
                for (int j = 0; j < 4; j++) fma2(acc2[i][j], ca[i], cb[j]);
            #pragma unroll
            for (int i = 0; i < 4; i++) ca[i] = ta[i];
            #pragma unroll
            for (int j = 0; j < 4; j++) cb[j] = tb[j];
        }
        #pragma unroll
        for (int i = 0; i < 4; i++)
            #pragma unroll
            for (int j = 0; j < 4; j++) fma2(acc2[i][j], ca[i], cb[j]);

        float rsum[4], csum[4];
        #pragma unroll
        for (int i = 0; i < 4; i++) rsum[i] = 0.f;
        #pragma unroll
        for (int j = 0; j < 4; j++) csum[j] = 0.f;

        #pragma unroll
        for (int i = 0; i < 4; i++) {
            int p = ty + 16 * i;
            #pragma unroll
            for (int j = 0; j < 4; j++) {
                int q = tx + 16 * j;
                float d = np[p] * nh[q];
                float c = red2(acc2[i][j]) / (d > EPSV ? d : EPSV);
                att [p * AST + q] = c;
                attT[q * AST + p] = c;
                rsum[i] += c;
                csum[j] += c;
            }
        }
        #pragma unroll
        for (int m = 1; m <= 8; m <<= 1)
            #pragma unroll
            for (int i = 0; i < 4; i++)
                rsum[i] += __shfl_xor_sync(0xffffffffu, rsum[i], m);
        if (tx == 0) {
            #pragma unroll
            for (int i = 0; i < 4; i++)
                rsumS[ty + 16 * i] = rsum[i];
        }
        #pragma unroll
        for (int j = 0; j < 4; j++)
            csum[j] += __shfl_xor_sync(0xffffffffu, csum[j], 16);
        if (lane < 16) {
            #pragma unroll
            for (int j = 0; j < 4; j++)
                redCS[(tx + 16 * j) * 8 + warp] = csum[j];
        }
    }
    __syncthreads();
    if (tid < 64) {
        float s0 = 0.f;
        #pragma unroll
        for (int k = 0; k < 8; k++) s0 += redCS[tid * 8 + k];
        csumS[tid] = s0;
    }
    __syncthreads();

    // ---- deriv phase: mean/max over the att axis, both sides, from smem ----
    if (tid < 200) {
        const int oi = tid / 25, hi = tid % 25;
        const int o0 = oi * 8;

        for (int side = 0; side < 2; side++) {
            const float* M  = (side == 0) ? att : attT;   // M[o][*]
            const float* V  = (side == 0) ? Hm  : P;      // V[*][h], stride HP
            const float* ds = (side == 0) ? rsumS : csumS;
            float* gmean = (side == 0 ? g_amean_h : g_amean_p)
                         + (size_t)(dir * B + b) * S * H;
            float* gmax  = (side == 0 ? g_amax_h  : g_amax_p )
                         + (size_t)(dir * B + b) * S * H;

            for (int ck = 0; ck < 2; ck++) {
                const int hb = ck * 100 + hi * 4;

                float ss[8][4], sx[8][4];
                #pragma unroll
                for (int io = 0; io < 8; io++)
                    #pragma unroll
                    for (int k = 0; k < 4; k++) { ss[io][k] = 0.f; sx[io][k] = -INFINITY; }

                for (int q2 = 0; q2 < 32; q2++) {
                    const int q = 2 * q2;
                    float2 av[8];
                    #pragma unroll
                    for (int io = 0; io < 8; io++)
                        av[io] = *reinterpret_cast<const float2*>(M + (o0 + io) * AST + q);
                    float2 va0 = *reinterpret_cast<const float2*>(V + q * HP + hb);
                    float2 va1 = *reinterpret_cast<const float2*>(V + q * HP + hb + 2);
                    float2 vb0 = *reinterpret_cast<const float2*>(V + (q + 1) * HP + hb);
                    float2 vb1 = *reinterpret_cast<const float2*>(V + (q + 1) * HP + hb + 2);
                    float vv0[4] = {va0.x, va0.y, va1.x, va1.y};
                    float vv1[4] = {vb0.x, vb0.y, vb1.x, vb1.y};
                    #pragma unroll
                    for (int io = 0; io < 8; io++) {
                        float ax = av[io].x, ay = av[io].y;
                        #pragma unroll
                        for (int k = 0; k < 4; k++) {
                            float t0 = ax * vv0[k];
                            float t1 = ay * vv1[k];
                            ss[io][k] += t0 + t1;
                            sx[io][k] = fmaxf(sx[io][k], fmaxf(t0, t1));
                        }
                    }
                }
                #pragma unroll
                for (int io = 0; io < 8; io++) {
                    float d = ds[o0 + io];
                    float inv = 1.f / (d > EPSV ? d : EPSV);
                    float4 m4, x4;
                    m4.x = ss[io][0] * inv; m4.y = ss[io][1] * inv;
                    m4.z = ss[io][2] * inv; m4.w = ss[io][3] * inv;
                    x4.x = sx[io][0]; x4.y = sx[io][1]; x4.z = sx[io][2]; x4.w = sx[io][3];
                    *reinterpret_cast<float4*>(gmean + (o0 + io) * H + hb) = m4;
                    *reinterpret_cast<float4*>(gmax  + (o0 + io) * H + hb) = x4;
                }
            }
        }
    }
}

// ================== Kernel B1: "full" mp_match (kind 0) =====================
// grid (B, 4, 2). V1 rows read straight from gmem (L2-resident); only the
// shared v2 row and W^2 are staged in smem -> high occupancy.
__global__ void __launch_bounds__(128)
match_full_kernel(const float* __restrict__ con_p,
                  const float* __restrict__ con_h,
                  const float* __restrict__ w1, const float* __restrict__ w2,
                  float* __restrict__ out) {
    extern __shared__ float sm[];
    float* V2 = sm;                 // WST (single row)
    float* W2 = V2 + WST;           // L*WST

    const int b = blockIdx.x;
    const int side = blockIdx.y >> 1;
    const int dir = blockIdx.y & 1;
    const int shalf = blockIdx.z;
    const int tid = threadIdx.x;
    const int s0 = shalf * 32;

    const float* v2 = (side == 0 ? con_h : con_p)
                    + (size_t)b * S * CS + (dir == 0 ? (S - 1) : 0) * CS + dir * H;
    for (int h2 = tid; h2 < 100; h2 += 128)
        *reinterpret_cast<float2*>(V2 + 2 * h2) =
            *reinterpret_cast<const float2*>(v2 + 2 * h2);

    const float* w = (dir == 0 ? w1 : w2);
    for (int i2 = tid; i2 < L * 100; i2 += 128) {
        int l = i2 / 100, h2 = i2 % 100;
        float2 wv = *reinterpret_cast<const float2*>(w + l * H + 2 * h2);
        float2 sq; sq.x = wv.x * wv.x; sq.y = wv.y * wv.y;
        *reinterpret_cast<float2*>(W2 + l * WST + 2 * h2) = sq;
    }
    __syncthreads();

    const int tx = tid & 3;        // l group: l = tx*5 + il
    const int ty = tid >> 2;       // s = s0 + ty

    const float* v1 = (side == 0 ? con_p : con_h)
                    + (size_t)b * S * CS + (size_t)(s0 + ty) * CS + dir * H;
    const ull* Ag = reinterpret_cast<const ull*>(v1);
    const ull* Bp = reinterpret_cast<const ull*>(V2);
    const ull* Wp[5];
    #pragma unroll
    for (int il = 0; il < 5; il++)
        Wp[il] = reinterpret_cast<const ull*>(W2 + (tx * 5 + il) * WST);

    ull dacc[5], naa[5], nbb[5];
    #pragma unroll
    for (int il = 0; il < 5; il++) { dacc[il] = 0ull; naa[il] = 0ull; nbb[il] = 0ull; }

    #pragma unroll 1
    for (int h2 = 0; h2 < 100; h2 += 4) {
        ull a[4];
        #pragma unroll
        for (int u = 0; u < 4; u++) a[u] = Ag[h2 + u];
        #pragma unroll
        for (int u = 0; u < 4; u++) {
            ull bb = Bp[h2 + u];
            ull u1 = mul2(a[u], bb), u2 = mul2(a[u], a[u]), u3 = mul2(bb, bb);
            #pragma unroll
            for (int il = 0; il < 5; il++) {
                ull wv = Wp[il][h2 + u];
                fma2(dacc[il], u1, wv);
                fma2(naa[il], u2, wv);
                fma2(nbb[il], u3, wv);
            }
        }
    }

    const int col = dir * 80;
    float* obase = out + (size_t)side * PSIZE + (size_t)b * S * MV;
    #pragma unroll
    for (int il = 0; il < 5; il++) {
        float d = sqrtf(red2(naa[il])) * sqrtf(red2(nbb[il]));
        obase[(s0 + ty) * MV + col + (tx * 5 + il)] = red2(dacc[il]) / fmaxf(d, EPSV);
    }
}

// ================ Kernel B2: att mean/max mp_match (kinds 1,2) ===============
// grid (B, 8, 2). V1/V2 rows read straight from gmem (L2-resident); only W^2
// staged in smem (16KB) -> ~6-7 blocks/SM, latency hidden by occupancy + MLP.
__global__ void __launch_bounds__(128)
match_att_kernel(const float* __restrict__ con_p,
                 const float* __restrict__ con_h,
                 const float* __restrict__ w5, const float* __restrict__ w6,
                 const float* __restrict__ w7, const float* __restrict__ w8,
                 float* __restrict__ out) {
    extern __shared__ float sm[];
    float* W2 = sm;                 // L*WST

    const int b = blockIdx.x;
    const int side = blockIdx.y >> 2;
    const int kind = 1 + ((blockIdx.y >> 1) & 1);
    const int dir = blockIdx.y & 1;
    const int shalf = blockIdx.z;
    const int tid = threadIdx.x;
    const int s0 = shalf * 32;

    const float* w = (kind == 1 ? (dir == 0 ? w5 : w6) : (dir == 0 ? w7 : w8));
    for (int i2 = tid; i2 < L * 100; i2 += 128) {
        int l = i2 / 100, h2 = i2 % 100;
        float2 wv = *reinterpret_cast<const float2*>(w + l * H + 2 * h2);
        float2 sq; sq.x = wv.x * wv.x; sq.y = wv.y * wv.y;
        *reinterpret_cast<float2*>(W2 + l * WST + 2 * h2) = sq;
    }
    __syncthreads();

    const int tx = tid & 3;
    const int ty = tid >> 2;
    const int s = s0 + ty;

    const float* v1 = (side == 0 ? con_p : con_h)
                    + (size_t)b * S * CS + (size_t)s * CS + dir * H;
    const float* v2 = (kind == 1 ? (side == 0 ? g_amean_h : g_amean_p)
                                 : (side == 0 ? g_amax_h  : g_amax_p))
                    + (size_t)(dir * B + b) * S * H + (size_t)s * H;
    const ull* Ag = reinterpret_cast<const ull*>(v1);
    const ull* Bg = reinterpret_cast<const ull*>(v2);
    const ull* Wp[5];
    #pragma unroll
    for (int il = 0; il < 5; il++)
        Wp[il] = reinterpret_cast<const ull*>(W2 + (tx * 5 + il) * WST);

    ull dacc[5], naa[5], nbb[5];
    #pragma unroll
    for (int il = 0; il < 5; il++) { dacc[il] = 0ull; naa[il] = 0ull; nbb[il] = 0ull; }

    #pragma unroll 1
    for (int h2 = 0; h2 < 100; h2 += 4) {
        ull a[4], bb[4];
        #pragma unroll
        for (int u = 0; u < 4; u++) { a[u] = Ag[h2 + u]; bb[u] = Bg[h2 + u]; }
        #pragma unroll
        for (int u = 0; u < 4; u++) {
            ull u1 = mul2(a[u], bb[u]), u2 = mul2(a[u], a[u]), u3 = mul2(bb[u], bb[u]);
            #pragma unroll
            for (int il = 0; il < 5; il++) {
                ull wv = Wp[il][h2 + u];
                fma2(dacc[il], u1, wv);
                fma2(naa[il], u2, wv);
                fma2(nbb[il], u3, wv);
            }
        }
    }

    const int col = (kind == 1 ? 40 : 60) + dir * 80;
    float* obase = out + (size_t)side * PSIZE + (size_t)b * S * MV;
    #pragma unroll
    for (int il = 0; il < 5; il++) {
        float d = sqrtf(red2(naa[il])) * sqrtf(red2(nbb[il]));
        obase[s * MV + col + (tx * 5 + il)] = red2(dacc[il]) / fmaxf(d, EPSV);
    }
}

// ================= Kernel C: pairwise mp + max reductions ====================
// grid (B, 10, 2): one block per (b, l-pair, dir). 256 threads, 4x4 (p,q) tile,
// RAW P/H in smem (l-independent) + per-l w^2 broadcast: D_l = sum w^2 * p * h.
__global__ void __launch_bounds__(256, 2)
pairwise_kernel(const float* __restrict__ con_p,
                const float* __restrict__ con_h,
                const float* __restrict__ w3,
                const float* __restrict__ w4,
                float* __restrict__ out) {
    extern __shared__ float sm[];
    float* P    = sm;                 // S*HP (raw p rows)
    float* Hm   = P  + S * HP;        // S*HP (raw h rows)
    float* W2   = Hm + S * HP;        // 2*HP (w^2 for the 2 perspectives)
    float* na   = W2 + 2 * HP;        // 2*S
    float* nb   = na + 2 * S;         // 2*S
    float* redQ = nb + 2 * S;         // 2*S*8

    const int b = blockIdx.x, lg = blockIdx.y, dir = blockIdx.z;
    const int l0 = lg * 2;
    const int tid = threadIdx.x;

    const float* w = (dir == 0 ? w3 : w4) + l0 * H;
    for (int i2 = tid; i2 < 2 * 100; i2 += 256) {
        int lr = i2 / 100, h2 = i2 % 100;
        float2 wv = *reinterpret_cast<const float2*>(w + lr * H + 2 * h2);
        float2 sq; sq.x = wv.x * wv.x; sq.y = wv.y * wv.y;
        *reinterpret_cast<float2*>(W2 + lr * HP + 2 * h2) = sq;
    }

    const float* pb = con_p + (size_t)b * S * CS + dir * H;
    const float* hb = con_h + (size_t)b * S * CS + dir * H;
    for (int i2 = tid; i2 < S * 100; i2 += 256) {
        int s = i2 / 100, h2 = i2 % 100;
        *reinterpret_cast<float2*>(P  + s * HP + 2 * h2) =
            *reinterpret_cast<const float2*>(pb + s * CS + 2 * h2);
        *reinterpret_cast<float2*>(Hm + s * HP + 2 * h2) =
            *reinterpret_cast<const float2*>(hb + s * CS + 2 * h2);
    }
    __syncthreads();

    // norms: 128 threads -> (row, lr) for a-side, 128 for b-side
    {
        int t = tid & 127;
        int row = t >> 1, lr = t & 1;
        const float* src = (tid < 128) ? (P + row * HP) : (Hm + row * HP);
        const float* wr  = W2 + lr * HP;
        float acc = 0.f;
        #pragma unroll 4
        for (int k = 0; k < 100; k++) {
            float2 v = *reinterpret_cast<const float2*>(src + 2 * k);
            float2 q = *reinterpret_cast<const float2*>(wr + 2 * k);
            acc += q.x * v.x * v.x + q.y * v.y * v.y;
        }
        if (tid < 128) na[lr * S + row] = sqrtf(acc);
        else           nb[lr * S + row] = sqrtf(acc);
    }
    __syncthreads();

    const int tx = tid & 15, ty = tid >> 4;
    const int lane = tid & 31, warp = tid >> 5;
    const ull* Ap[4]; const ull* Bp[4];
    #pragma unroll
    for (int i = 0; i < 4; i++) Ap[i] = reinterpret_cast<const ull*>(P  + (ty + 16 * i) * HP);
    #pragma unroll
    for (int j = 0; j < 4; j++) Bp[j] = reinterpret_cast<const ull*>(Hm + (tx + 16 * j) * HP);
    const ull* W0 = reinterpret_cast<const ull*>(W2);
    const ull* W1 = reinterpret_cast<const ull*>(W2 + HP);

    ull acc2[2][4][4];
    #pragma unroll
    for (int lr = 0; lr < 2; lr++)
        #pragma unroll
        for (int i = 0; i < 4; i++)
            #pragma unroll
            for (int j = 0; j < 4; j++) acc2[lr][i][j] = 0ull;

    #pragma unroll 2
    for (int h2 = 0; h2 < 100; h2++) {
        ull pa[4], hbv[4];
        #pragma unroll
        for (int i = 0; i < 4; i++) pa[i] = Ap[i][h2];
        #pragma unroll
        for (int j = 0; j < 4; j++) hbv[j] = Bp[j][h2];
        ull w20 = W0[h2], w21 = W1[h2];
        ull sa[4];
        #pragma unroll
        for (int i = 0; i < 4; i++) sa[i] = mul2(pa[i], w20);
        #pragma unroll
        for (int i = 0; i < 4; i++)
            #pragma unroll
            for (int j = 0; j < 4; j++) fma2(acc2[0][i][j], sa[i], hbv[j]);
        #pragma unroll
        for (int i = 0; i < 4; i++) sa[i] = mul2(pa[i], w21);
        #pragma unroll
        for (int i = 0; i < 4; i++)
            #pragma unroll
            for (int j = 0; j < 4; j++) fma2(acc2[1][i][j], sa[i], hbv[j]);
    }

    #pragma unroll
    for (int lr = 0; lr < 2; lr++) {
        float pmax[4], qmax[4];
        #pragma unroll
        for (int i = 0; i < 4; i++) pmax[i] = -INFINITY;
        #pragma unroll
        for (int j = 0; j < 4; j++) qmax[j] = -INFINITY;

        #pragma unroll
        for (int i = 0; i < 4; i++) {
            int p = ty + 16 * i;
            #pragma unroll
            for (int j = 0; j < 4; j++) {
                int q = tx + 16 * j;
                float d = na[lr * S + p] * nb[lr * S + q];
                float c = red2(acc2[lr][i][j]) / (d > EPSV ? d : EPSV);
                pmax[i] = fmaxf(pmax[i], c);
                qmax[j] = fmaxf(qmax[j], c);
            }
        }
        const int colbase = (dir == 0 ? 20 : 100) + l0 + lr;
        #pragma unroll
        for (int m = 1; m <= 8; m <<= 1)
            #pragma unroll
            for (int i = 0; i < 4; i++)
                pmax[i] = fmaxf(pmax[i], __shfl_xor_sync(0xffffffffu, pmax[i], m));
        if (tx == 0) {
            #pragma unroll
            for (int i = 0; i < 4; i++)
                out[((size_t)b * S + (ty + 16 * i)) * MV + colbase] = pmax[i]; // mv_p
        }
        #pragma unroll
        for (int j = 0; j < 4; j++)
            qmax[j] = fmaxf(qmax[j], __shfl_xor_sync(0xffffffffu, qmax[j], 16));
        if (lane < 16) {
            #pragma unroll
            for (int j = 0; j < 4; j++)
                redQ[(lr * S + tx + 16 * j) * 8 + warp] = qmax[j];
        }
    }
    __syncthreads();
    if (tid < 128) {
        int lr = tid >> 6, q = tid & 63;
        float m = -INFINITY;
        #pragma unroll
        for (int k = 0; k < 8; k++) m = fmaxf(m, redQ[(lr * S + q) * 8 + k]);
        const int colbase = (dir == 0 ? 20 : 100) + l0 + lr;
        out[(size_t)PSIZE + ((size_t)b * S + q) * MV + colbase] = m;          // mv_h
    }
}

// ================================ launcher ===================================
extern "C" void kernel_launch(void* const* d_in, const int* in_sizes, int n_in,
                              void* d_out, int out_size) {
    const float* con_p = (const float*)d_in[0];
    const float* con_h = (const float*)d_in[1];
    const float* w1 = (const float*)d_in[2];
    const float* w2 = (const float*)d_in[3];
    const float* w3 = (const float*)d_in[4];
    const float* w4 = (const float*)d_in[5];
    const float* w5 = (const float*)d_in[6];
    const float* w6 = (const float*)d_in[7];
    const float* w7 = (const float*)d_in[8];
    const float* w8 = (const float*)d_in[9];
    float* out = (float*)d_out;

    constexpr size_t SM_AD = (size_t)(2 * S * HP + 2 * S * AST + 4 * S + S * 8) * sizeof(float);
    constexpr size_t SM_BF = (size_t)(WST + L * WST) * sizeof(float);
    constexpr size_t SM_BA = (size_t)(L * WST) * sizeof(float);
    constexpr size_t SM_C  = (size_t)(2 * S * HP + 2 * HP + 4 * S + 2 * S * 8) * sizeof(float);

    static cudaStream_t s2 = nullptr;
    static cudaEvent_t evFork = nullptr, evJoin = nullptr;
    static bool init_done = false;
    if (!init_done) {
        cudaFuncSetAttribute(attnderiv_kernel,  cudaFuncAttributeMaxDynamicSharedMemorySize, (int)SM_AD);
        cudaFuncSetAttribute(match_full_kernel, cudaFuncAttributeMaxDynamicSharedMemorySize, (int)SM_BF);
        cudaFuncSetAttribute(match_att_kernel,  cudaFuncAttributeMaxDynamicSharedMemorySize, (int)SM_BA);
        cudaFuncSetAttribute(pairwise_kernel,   cudaFuncAttributeMaxDynamicSharedMemorySize, (int)SM_C);
        cudaStreamCreateWithFlags(&s2, cudaStreamNonBlocking);
        cudaEventCreateWithFlags(&evFork, cudaEventDisableTiming);
        cudaEventCreateWithFlags(&evJoin, cudaEventDisableTiming);
        init_done = true;
    }

    // s2: pairwise (out cols 20-39/100-119) then match_full (cols 0-19/80-99).
    // stream 0: fused attn+deriv -> match_att (cols 40-79/120-159).
    cudaEventRecord(evFork, 0);
    cudaStreamWaitEvent(s2, evFork, 0);
    pairwise_kernel<<<dim3(B, 10, 2), 256, SM_C, s2>>>(con_p, con_h, w3, w4, out);
    match_full_kernel<<<dim3(B, 4, 2), 128, SM_BF, s2>>>(con_p, con_h, w1, w2, out);

    attnderiv_kernel<<<dim3(B, 2), 256, SM_AD>>>(con_p, con_h);
    match_att_kernel<<<dim3(B, 8, 2), 128, SM_BA>>>(con_p, con_h, w5, w6, w7, w8, out);

    cudaEventRecord(evJoin, s2);
    cudaStreamWaitEvent(0, evJoin, 0);
}